// round 12
// baseline (speedup 1.0000x reference)
#include <cuda_runtime.h>
#include <cuda_bf16.h>
#include <cstdint>
#include <math.h>

#define BB 2
#define SS 2048
#define HH 32
#define HD 64
#define MD 2048
#define MTOT (BB*SS)

// ---------------- device scratch (static, no allocation) ----------------
__device__ __nv_bfloat16 gx_h[MTOT*MD],  gx_l[MTOT*MD];
__device__ __nv_bfloat16 gwq_h[MD*MD],   gwq_l[MD*MD];
__device__ __nv_bfloat16 gwk_h[MD*MD],   gwk_l[MD*MD];
__device__ __nv_bfloat16 gwv_h[MD*MD],   gwv_l[MD*MD];
__device__ __nv_bfloat16 gwo_h[MD*MD],   gwo_l[MD*MD];
__device__ __nv_bfloat16 gq_h[MTOT*MD],  gq_l[MTOT*MD];   // [bh][s][64]
__device__ __nv_bfloat16 gk_h[MTOT*MD],  gk_l[MTOT*MD];
__device__ __nv_bfloat16 gv_h[MTOT*MD],  gv_l[MTOT*MD];
__device__ __nv_bfloat16 gc_h[MTOT*MD],  gc_l[MTOT*MD];   // ctx [b*S+s][2048]
__device__ float g_biastab[HH*4096];

// ---------------- small helpers ----------------
__device__ __forceinline__ uint32_t smem_to_u32(const void* p) {
    uint32_t a;
    asm("{ .reg .u64 t; cvta.to.shared.u64 t, %1; cvt.u32.u64 %0, t; }" : "=r"(a) : "l"(p));
    return a;
}
__device__ __forceinline__ void cp16(uint32_t dst, const void* src) {
    asm volatile("cp.async.cg.shared.global [%0], [%1], 16;" :: "r"(dst), "l"(src));
}
__device__ __forceinline__ void cp4(uint32_t dst, const void* src) {
    asm volatile("cp.async.ca.shared.global [%0], [%1], 4;" :: "r"(dst), "l"(src));
}
#define CP_COMMIT() asm volatile("cp.async.commit_group;" ::: "memory")
#define CP_WAIT(n)  asm volatile("cp.async.wait_group %0;" :: "n"(n) : "memory")

__device__ __forceinline__ void ldx4(uint32_t* r, uint32_t addr) {
    asm volatile("ldmatrix.sync.aligned.m8n8.x4.shared.b16 {%0,%1,%2,%3}, [%4];"
                 : "=r"(r[0]), "=r"(r[1]), "=r"(r[2]), "=r"(r[3]) : "r"(addr));
}
__device__ __forceinline__ void ldx4t(uint32_t* r, uint32_t addr) {
    asm volatile("ldmatrix.sync.aligned.m8n8.x4.trans.shared.b16 {%0,%1,%2,%3}, [%4];"
                 : "=r"(r[0]), "=r"(r[1]), "=r"(r[2]), "=r"(r[3]) : "r"(addr));
}
__device__ __forceinline__ void mma_bf16(float* d, const uint32_t* a,
                                         uint32_t b0, uint32_t b1) {
    asm volatile(
        "mma.sync.aligned.m16n8k16.row.col.f32.bf16.bf16.f32 "
        "{%0,%1,%2,%3}, {%4,%5,%6,%7}, {%8,%9}, {%0,%1,%2,%3};"
        : "+f"(d[0]), "+f"(d[1]), "+f"(d[2]), "+f"(d[3])
        : "r"(a[0]), "r"(a[1]), "r"(a[2]), "r"(a[3]), "r"(b0), "r"(b1));
}

__device__ __forceinline__ uint32_t pack_hi(float a, float b) {
    return __byte_perm(__float_as_uint(a), __float_as_uint(b), 0x7632);
}
__device__ __forceinline__ uint32_t pack_lo_res(float a, float b) {
    float ra = a - __uint_as_float(__float_as_uint(a) & 0xffff0000u);
    float rb = b - __uint_as_float(__float_as_uint(b) & 0xffff0000u);
    uint32_t r;
    asm("cvt.rn.bf16x2.f32 %0, %1, %2;" : "=r"(r) : "f"(rb), "f"(ra));
    return r;
}

// fp32 -> bf16 hi/lo split; each thread handles 8 floats, uint4 stores
__global__ void convert_kernel(const float* __restrict__ in,
                               __nv_bfloat16* __restrict__ hi,
                               __nv_bfloat16* __restrict__ lo, int n8) {
    int i = blockIdx.x * blockDim.x + threadIdx.x;
    if (i >= n8) return;
    float4 f0 = reinterpret_cast<const float4*>(in)[2*i];
    float4 f1 = reinterpret_cast<const float4*>(in)[2*i + 1];
    reinterpret_cast<uint4*>(hi)[i] = make_uint4(
        pack_hi(f0.x, f0.y), pack_hi(f0.z, f0.w),
        pack_hi(f1.x, f1.y), pack_hi(f1.z, f1.w));
    reinterpret_cast<uint4*>(lo)[i] = make_uint4(
        pack_lo_res(f0.x, f0.y), pack_lo_res(f0.z, f0.w),
        pack_lo_res(f1.x, f1.y), pack_lo_res(f1.z, f1.w));
}

// 256-thread loader (attention KV, 128B rows): thread = (row t>>1, half t&1)
__device__ __forceinline__ void issue4(uint32_t sb,
    const __nv_bfloat16* s0, const __nv_bfloat16* s1,
    const __nv_bfloat16* s2, const __nv_bfloat16* s3, int tid)
{
    const int r2 = tid >> 1, hf = tid & 1;
    const uint32_t dd = (uint32_t)(r2 * 128 + hf * 64);
    #pragma unroll
    for (int i = 0; i < 4; i++) {
        uint32_t o = dd + i * 16; o ^= (o >> 3) & 0x70;
        cp16(sb + o,         s0 + i * 8);
        cp16(sb + 16384 + o, s1 + i * 8);
        cp16(sb + 32768 + o, s2 + i * 8);
        cp16(sb + 49152 + o, s3 + i * 8);
    }
}

// ===========================================================================
// bf16x3 GEMM v5: 256 threads / 8 warps (4m x 2n), warp tile 32x64,
// 128x128 CTA tile, K-chunk 32, 3-stage pipeline (96KB) -> 2 CTAs/SM.
// TERM-MAJOR MMA ordering: same-accumulator reuse distance 8 (was 1),
// so HMMA latency is covered by ILP instead of stalling the warp.
// stage layout: Ah 8K | Al 8K | Bh 8K | Bl 8K = 32K
// ===========================================================================
#define GSTAGE 32768
#define GSMEM_BYTES (3 * GSTAGE)

struct GemmCtx {
    uint32_t su;
    int tid, l, w, wm, wn, grp, lr;
    uint32_t a_row[2], b_row[4], a_c16, b_c16;
};

__device__ __forceinline__ void gemm_init(GemmCtx& g, char* smem) {
    g.su = smem_to_u32(smem);
    g.tid = threadIdx.x;
    g.l = g.tid & 31; g.w = g.tid >> 5;
    g.wm = g.w >> 1;  g.wn = g.w & 1;          // 4m x 2n warp grid
    g.grp = g.l >> 3; g.lr = g.l & 7;
    #pragma unroll
    for (int mt = 0; mt < 2; mt++)
        g.a_row[mt] = (uint32_t)((g.wm * 32 + mt * 16 + g.lr + (g.grp & 1) * 8) * 64);
    #pragma unroll
    for (int j = 0; j < 4; j++)
        g.b_row[j] = (uint32_t)((g.wn * 64 + j * 16 + g.lr + (g.grp >> 1) * 8) * 64);
    g.a_c16 = (uint32_t)(g.grp >> 1) * 16;
    g.b_c16 = (uint32_t)(g.grp & 1) * 16;
}

// per-stage load: A 128x32 + B 128x32 (hi+lo), 256 threads, 8 cp16/thread.
__device__ __forceinline__ void issue_g(uint32_t sb,
    const __nv_bfloat16* a_h, const __nv_bfloat16* a_l,
    const __nv_bfloat16* b_h, const __nv_bfloat16* b_l, int tid)
{
    uint32_t o = (uint32_t)((tid >> 1) * 64 + (tid & 1) * 32);
    uint32_t o0 = o ^ ((o >> 3) & 0x30);
    uint32_t o1 = o0 ^ 16;
    cp16(sb + o0,         a_h);     cp16(sb + o1,         a_h + 8);
    cp16(sb + 8192  + o0, a_l);     cp16(sb + 8192  + o1, a_l + 8);
    cp16(sb + 16384 + o0, b_h);     cp16(sb + 16384 + o1, b_h + 8);
    cp16(sb + 24576 + o0, b_l);     cp16(sb + 24576 + o1, b_l + 8);
}

__device__ __forceinline__ void gemm_body(
    GemmCtx& g,
    const __nv_bfloat16* pa_h, const __nv_bfloat16* pa_l,
    const __nv_bfloat16* pb_h, const __nv_bfloat16* pb_l,
    float acc[2][8][4])
{
    issue_g(g.su,          pa_h,      pa_l,      pb_h,      pb_l,      g.tid); CP_COMMIT();
    issue_g(g.su + GSTAGE, pa_h + 32, pa_l + 32, pb_h + 32, pb_l + 32, g.tid); CP_COMMIT();

    for (int c = 0; c < 64; c++) {
        CP_WAIT(1);
        __syncthreads();
        if (c + 2 < 64) {
            int k0 = (c + 2) * 32;
            issue_g(g.su + (uint32_t)((c + 2) % 3) * GSTAGE,
                    pa_h + k0, pa_l + k0, pb_h + k0, pb_l + k0, g.tid);
        }
        CP_COMMIT();

        const uint32_t cur = g.su + (uint32_t)(c % 3) * GSTAGE;

        #pragma unroll
        for (int ks = 0; ks < 2; ks++) {
            uint32_t ah[2][4], al[2][4];
            #pragma unroll
            for (int mt = 0; mt < 2; mt++) {
                uint32_t off = g.a_row[mt] + (uint32_t)(ks * 32) + g.a_c16;
                off ^= (off >> 3) & 0x30;
                ldx4(ah[mt], cur + off);
                ldx4(al[mt], cur + 8192 + off);
            }
            // process B subtiles in pairs (jp), term-major within each pair
            #pragma unroll
            for (int jp = 0; jp < 2; jp++) {
                uint32_t bh[2][4], bl[2][4];
                #pragma unroll
                for (int u = 0; u < 2; u++) {
                    uint32_t off = g.b_row[2*jp + u] + (uint32_t)(ks * 32) + g.b_c16;
                    off ^= (off >> 3) & 0x30;
                    ldx4(bh[u], cur + 16384 + off);
                    ldx4(bl[u], cur + 24576 + off);
                }
                // term hh: 8 independent MMAs
                #pragma unroll
                for (int u = 0; u < 2; u++)
                    #pragma unroll
                    for (int mt = 0; mt < 2; mt++) {
                        mma_bf16(acc[mt][4*jp + 2*u],     ah[mt], bh[u][0], bh[u][1]);
                        mma_bf16(acc[mt][4*jp + 2*u + 1], ah[mt], bh[u][2], bh[u][3]);
                    }
                // term hl
                #pragma unroll
                for (int u = 0; u < 2; u++)
                    #pragma unroll
                    for (int mt = 0; mt < 2; mt++) {
                        mma_bf16(acc[mt][4*jp + 2*u],     ah[mt], bl[u][0], bl[u][1]);
                        mma_bf16(acc[mt][4*jp + 2*u + 1], ah[mt], bl[u][2], bl[u][3]);
                    }
                // term lh
                #pragma unroll
                for (int u = 0; u < 2; u++)
                    #pragma unroll
                    for (int mt = 0; mt < 2; mt++) {
                        mma_bf16(acc[mt][4*jp + 2*u],     al[mt], bh[u][0], bh[u][1]);
                        mma_bf16(acc[mt][4*jp + 2*u + 1], al[mt], bh[u][2], bh[u][3]);
                    }
            }
        }
    }
}

// ---- fused QKV: grid 1536 = 3 x 512 tiles (wsel-major), PERM bf16 output ----
__global__ void __launch_bounds__(256, 2) gemm_qkv()
{
    extern __shared__ char smem[];
    GemmCtx g; gemm_init(g, smem);

    const int wsel = blockIdx.x >> 9;
    const int tile = blockIdx.x & 511;
    const int m0 = (tile >> 4) * 128, n0 = (tile & 15) * 128;

    const __nv_bfloat16 *Bh, *Bl;
    __nv_bfloat16 *Ch, *Cl;
    if (wsel == 0)      { Bh = gwq_h; Bl = gwq_l; Ch = gq_h; Cl = gq_l; }
    else if (wsel == 1) { Bh = gwk_h; Bl = gwk_l; Ch = gk_h; Cl = gk_l; }
    else                { Bh = gwv_h; Bl = gwv_l; Ch = gv_h; Cl = gv_l; }

    const int sr = g.tid >> 1, sc = (g.tid & 1) * 16;
    const __nv_bfloat16* pa_h = gx_h + (size_t)(m0 + sr) * 2048 + sc;
    const __nv_bfloat16* pa_l = gx_l + (size_t)(m0 + sr) * 2048 + sc;
    const __nv_bfloat16* pb_h = Bh   + (size_t)(n0 + sr) * 2048 + sc;
    const __nv_bfloat16* pb_l = Bl   + (size_t)(n0 + sr) * 2048 + sc;

    float acc[2][8][4];
    #pragma unroll
    for (int mt = 0; mt < 2; mt++)
        #pragma unroll
        for (int nt = 0; nt < 8; nt++)
            #pragma unroll
            for (int i = 0; i < 4; i++) acc[mt][nt][i] = 0.f;

    gemm_body(g, pa_h, pa_l, pb_h, pb_l, acc);

    #pragma unroll
    for (int mt = 0; mt < 2; mt++) {
        #pragma unroll
        for (int nt = 0; nt < 8; nt++) {
            int r  = m0 + g.wm * 32 + mt * 16 + (g.l >> 2);
            int cc = n0 + g.wn * 64 + nt * 8 + 2 * (g.l & 3);
            int b = r >> 11, s = r & 2047, h = cc >> 6, d = cc & 63;
            size_t base = (((size_t)(b * 32 + h)) * 2048 + s) * 64 + d;
            *reinterpret_cast<uint32_t*>(Ch + base) =
                pack_hi(acc[mt][nt][0], acc[mt][nt][1]);
            *reinterpret_cast<uint32_t*>(Cl + base) =
                pack_lo_res(acc[mt][nt][0], acc[mt][nt][1]);
            *reinterpret_cast<uint32_t*>(Ch + base + 8 * 64) =
                pack_hi(acc[mt][nt][2], acc[mt][nt][3]);
            *reinterpret_cast<uint32_t*>(Cl + base + 8 * 64) =
                pack_lo_res(acc[mt][nt][2], acc[mt][nt][3]);
        }
    }
}

// ---- output projection: fp32 C, grid 512 ----
__global__ void __launch_bounds__(256, 2) gemm_out(float* __restrict__ Cf)
{
    extern __shared__ char smem[];
    GemmCtx g; gemm_init(g, smem);
    const int m0 = (blockIdx.x >> 4) * 128, n0 = (blockIdx.x & 15) * 128;

    const int sr = g.tid >> 1, sc = (g.tid & 1) * 16;
    const __nv_bfloat16* pa_h = gc_h  + (size_t)(m0 + sr) * 2048 + sc;
    const __nv_bfloat16* pa_l = gc_l  + (size_t)(m0 + sr) * 2048 + sc;
    const __nv_bfloat16* pb_h = gwo_h + (size_t)(n0 + sr) * 2048 + sc;
    const __nv_bfloat16* pb_l = gwo_l + (size_t)(n0 + sr) * 2048 + sc;

    float acc[2][8][4];
    #pragma unroll
    for (int mt = 0; mt < 2; mt++)
        #pragma unroll
        for (int nt = 0; nt < 8; nt++)
            #pragma unroll
            for (int i = 0; i < 4; i++) acc[mt][nt][i] = 0.f;

    gemm_body(g, pa_h, pa_l, pb_h, pb_l, acc);

    #pragma unroll
    for (int mt = 0; mt < 2; mt++) {
        #pragma unroll
        for (int nt = 0; nt < 8; nt++) {
            int r  = m0 + g.wm * 32 + mt * 16 + (g.l >> 2);
            int cc = n0 + g.wn * 64 + nt * 8 + 2 * (g.l & 3);
            *reinterpret_cast<float2*>(Cf + (size_t)r * 2048 + cc) =
                make_float2(acc[mt][nt][0], acc[mt][nt][1]);
            *reinterpret_cast<float2*>(Cf + (size_t)(r + 8) * 2048 + cc) =
                make_float2(acc[mt][nt][2], acc[mt][nt][3]);
        }
    }
}

// ===========================================================================
// relative-position bucket (exact integer T5 formula) + bias table
// ===========================================================================
__device__ __forceinline__ int rel_bucket(int dist) {
    int rel = dist > 0 ? 16 : 0;
    int d = abs(dist);
    int sb;
    if (d < 8)       sb = d;
    else if (d < 12) sb = 8;
    else if (d < 16) sb = 9;
    else if (d < 23) sb = 10;
    else if (d < 32) sb = 11;
    else if (d < 46) sb = 12;
    else if (d < 64) sb = 13;
    else if (d < 91) sb = 14;
    else             sb = 15;
    return rel + sb;
}

__global__ void bias_table_kernel(const float* __restrict__ rel_bias) {
    int idx = blockIdx.x * blockDim.x + threadIdx.x;
    if (idx >= HH * 4095) return;
    int h = idx / 4095;
    int di = idx % 4095;
    g_biastab[h * 4096 + di] = rel_bias[rel_bucket(di - 2047) * HH + h];
}

// ===========================================================================
// FA2-style attention, bf16x3, KV tile 128 (16 iters) + folded bias write.
// TERM-MAJOR MMA ordering in QK and PV (same-acc reuse distance 4, was 1).
// smem: Qh 16K | Ql 16K | 2 x { Kh Kl Vh Vl } 64K | 2 x bias 1K = 162K
// ===========================================================================
#define ASMEM_BYTES (32768 + 2*65536 + 2*1024)

__global__ void __launch_bounds__(256, 1) attn_mma(
    __nv_bfloat16* __restrict__ Ch, __nv_bfloat16* __restrict__ Cl,
    float* __restrict__ out_bias)
{
    extern __shared__ char smem[];
    const uint32_t su = smem_to_u32(smem);
    const int tid = threadIdx.x, l = tid & 31, w = tid >> 5;
    const int grp = l >> 3, lr = l & 7;
    const int bh = blockIdx.y, h = bh & 31, b = bh >> 5;
    const int q0 = blockIdx.x * 128;
    const size_t bhoff = (size_t)bh * SS * HD;
    const int r2 = tid >> 1, hf = tid & 1;

    // Q tiles -> smem (part of group 0)
    {
        const __nv_bfloat16* sh = gq_h + bhoff + (size_t)(q0 + r2) * 64 + hf * 32;
        const __nv_bfloat16* sl = gq_l + bhoff + (size_t)(q0 + r2) * 64 + hf * 32;
        uint32_t dd = (uint32_t)(r2 * 128 + hf * 64);
        #pragma unroll
        for (int i = 0; i < 4; i++) {
            uint32_t o = dd + i * 16; o ^= (o >> 3) & 0x70;
            cp16(su + o,         sh + i * 8);
            cp16(su + 16384 + o, sl + i * 8);
        }
    }

    // KV + bias issue for ktile kt
    auto issue_kv = [&](int kt) {
        uint32_t sb = su + 32768 + (uint32_t)(kt & 1) * 65536;
        size_t off = bhoff + (size_t)(kt * 128 + r2) * 64 + hf * 32;
        issue4(sb, gk_h + off, gk_l + off, gv_h + off, gv_l + off, tid);
        int w0 = kt * 128 - q0 + 1920;
        cp4(su + 163840 + (uint32_t)(kt & 1) * 1024 + tid * 4,
            &g_biastab[h * 4096 + w0 + tid]);
    };
    issue_kv(0); CP_COMMIT();
    issue_kv(1); CP_COMMIT();

    float o[8][4];
    #pragma unroll
    for (int nt = 0; nt < 8; nt++)
        #pragma unroll
        for (int i = 0; i < 4; i++) o[nt][i] = 0.f;
    float mrow[2] = {-1e30f, -1e30f};
    float lrow[2] = {0.f, 0.f};

    const uint32_t qbase  = (uint32_t)((w * 16 + lr + (grp & 1) * 8) * 128 + (grp >> 1) * 16);
    const uint32_t kvbase = (uint32_t)((lr + (grp >> 1) * 8) * 128 + (grp & 1) * 16);

    for (int kt = 0; kt < 16; kt++) {
        CP_WAIT(1);
        __syncthreads();
        const uint32_t SB = su + 32768 + (uint32_t)(kt & 1) * 65536;
        const float* bsm = reinterpret_cast<const float*>(smem + 163840 + (kt & 1) * 1024);

        // ---- S = Q K^T (bf16x3, term-major per K-subtile pair) ----
        float s[16][4];
        #pragma unroll
        for (int j = 0; j < 16; j++)
            #pragma unroll
            for (int i = 0; i < 4; i++) s[j][i] = 0.f;

        #pragma unroll
        for (int ks = 0; ks < 4; ks++) {
            uint32_t qo = qbase + (uint32_t)(ks * 32); qo ^= (qo >> 3) & 0x70;
            uint32_t ah[4], al[4];
            ldx4(ah, su + qo);
            ldx4(al, su + 16384 + qo);
            #pragma unroll
            for (int jp = 0; jp < 4; jp++) {      // pairs of K subtiles
                uint32_t kh[2][4], kl[2][4];
                #pragma unroll
                for (int u = 0; u < 2; u++) {
                    uint32_t ko = kvbase + (uint32_t)((2*jp + u) * 2048 + ks * 32);
                    ko ^= (ko >> 3) & 0x70;
                    ldx4(kh[u], SB + ko);
                    ldx4(kl[u], SB + 16384 + ko);
                }
                // hh
                #pragma unroll
                for (int u = 0; u < 2; u++) {
                    mma_bf16(s[4*jp + 2*u],     ah, kh[u][0], kh[u][1]);
                    mma_bf16(s[4*jp + 2*u + 1], ah, kh[u][2], kh[u][3]);
                }
                // hl
                #pragma unroll
                for (int u = 0; u < 2; u++) {
                    mma_bf16(s[4*jp + 2*u],     ah, kl[u][0], kl[u][1]);
                    mma_bf16(s[4*jp + 2*u + 1], ah, kl[u][2], kl[u][3]);
                }
                // lh
                #pragma unroll
                for (int u = 0; u < 2; u++) {
                    mma_bf16(s[4*jp + 2*u],     al, kh[u][0], kh[u][1]);
                    mma_bf16(s[4*jp + 2*u + 1], al, kh[u][2], kh[u][3]);
                }
            }
        }

        // ---- bias + online softmax ----
        const int bb = 127 - (w * 16 + (l >> 2)) + 2 * (l & 3);
        #pragma unroll
        for (int j = 0; j < 16; j++) {
            s[j][0] += bsm[bb + 8*j];
            s[j][1] += bsm[bb + 8*j + 1];
            s[j][2] += bsm[bb + 8*j - 8];
            s[j][3] += bsm[bb + 8*j - 7];
        }
        #pragma unroll
        for (int u = 0; u < 2; u++) {
            float mx = -1e30f;
            #pragma unroll
            for (int j = 0; j < 16; j++)
                mx = fmaxf(mx, fmaxf(s[j][2*u], s[j][2*u+1]));
            mx = fmaxf(mx, __shfl_xor_sync(0xffffffffu, mx, 1));
            mx = fmaxf(mx, __shfl_xor_sync(0xffffffffu, mx, 2));
            float mnew = fmaxf(mrow[u], mx);
            float scale = __expf(mrow[u] - mnew);
            mrow[u] = mnew;
            float sum = 0.f;
            #pragma unroll
            for (int j = 0; j < 16; j++) {
                float p0 = __expf(s[j][2*u]   - mnew);
                float p1 = __expf(s[j][2*u+1] - mnew);
                s[j][2*u] = p0; s[j][2*u+1] = p1;
                sum += p0 + p1;
            }
            sum += __shfl_xor_sync(0xffffffffu, sum, 1);
            sum += __shfl_xor_sync(0xffffffffu, sum, 2);
            lrow[u] = lrow[u] * scale + sum;
            #pragma unroll
            for (int nt = 0; nt < 8; nt++) {
                o[nt][2*u]   *= scale;
                o[nt][2*u+1] *= scale;
            }
        }

        // ---- O += P V (bf16x3, term-major per V-subtile pair) ----
        #pragma unroll
        for (int ks = 0; ks < 8; ks++) {
            uint32_t aph[4], apl[4];
            aph[0] = pack_hi(s[2*ks][0],   s[2*ks][1]);
            aph[1] = pack_hi(s[2*ks][2],   s[2*ks][3]);
            aph[2] = pack_hi(s[2*ks+1][0], s[2*ks+1][1]);
            aph[3] = pack_hi(s[2*ks+1][2], s[2*ks+1][3]);
            apl[0] = pack_lo_res(s[2*ks][0],   s[2*ks][1]);
            apl[1] = pack_lo_res(s[2*ks][2],   s[2*ks][3]);
            apl[2] = pack_lo_res(s[2*ks+1][0], s[2*ks+1][1]);
            apl[3] = pack_lo_res(s[2*ks+1][2], s[2*ks+1][3]);
            #pragma unroll
            for (int dp = 0; dp < 2; dp++) {      // pairs of V subtiles
                uint32_t vh[2][4], vl[2][4];
                #pragma unroll
                for (int u = 0; u < 2; u++) {
                    uint32_t vo = kvbase + (uint32_t)(ks * 2048 + (2*dp + u) * 32);
                    vo ^= (vo >> 3) & 0x70;
                    ldx4t(vh[u], SB + 32768 + vo);
                    ldx4t(vl[u], SB + 49152 + vo);
                }
                // ph·vh
                #pragma unroll
                for (int u = 0; u < 2; u++) {
                    mma_bf16(o[4*dp + 2*u],     aph, vh[u][0], vh[u][2]);
                    mma_bf16(o[4*dp + 2*u + 1], aph, vh[u][1], vh[u][3]);
                }
                // ph·vl
                #pragma unroll
                for (int u = 0; u < 2; u++) {
                    mma_bf16(o[4*dp + 2*u],     aph, vl[u][0], vl[u][2]);
                    mma_bf16(o[4*dp + 2*u + 1], aph, vl[u][1], vl[u][3]);
                }
                // pl·vh
                #pragma unroll
                for (int u = 0; u < 2; u++) {
                    mma_bf16(o[4*dp + 2*u],     apl, vh[u][0], vh[u][2]);
                    mma_bf16(o[4*dp + 2*u + 1], apl, vh[u][1], vh[u][3]);
                }
            }
        }

        // ---- folded position_bias materialization (b==0 CTAs only) ----
        if (b == 0) {
            const int q = tid >> 1;          // 0..127
            const int kh2 = (tid & 1) * 64;  // 0 or 64
            float* dst = out_bias + ((size_t)h * 2048 + (q0 + q)) * 2048
                                  + kt * 128 + kh2;
            const int bidx = kh2 - q + 127;
            #pragma unroll
            for (int i = 0; i < 16; i++) {
                *reinterpret_cast<float4*>(dst + 4*i) =
                    make_float4(bsm[bidx + 4*i],     bsm[bidx + 4*i + 1],
                                bsm[bidx + 4*i + 2], bsm[bidx + 4*i + 3]);
            }
        }

        __syncthreads();
        if (kt + 2 < 16) issue_kv(kt + 2);
        CP_COMMIT();
    }

    // ---- epilogue: normalize, hi/lo split, store ctx ----
    const float inv0 = 1.f / lrow[0], inv1 = 1.f / lrow[1];
    const int rg0 = b * 2048 + q0 + w * 16 + (l >> 2);
    const size_t base0 = (size_t)rg0 * 2048 + h * 64 + 2 * (l & 3);
    const size_t base1 = base0 + (size_t)8 * 2048;
    #pragma unroll
    for (int nt = 0; nt < 8; nt++) {
        float a0 = o[nt][0] * inv0, a1 = o[nt][1] * inv0;
        float a2 = o[nt][2] * inv1, a3 = o[nt][3] * inv1;
        *reinterpret_cast<uint32_t*>(Ch + base0 + nt * 8) = pack_hi(a0, a1);
        *reinterpret_cast<uint32_t*>(Cl + base0 + nt * 8) = pack_lo_res(a0, a1);
        *reinterpret_cast<uint32_t*>(Ch + base1 + nt * 8) = pack_hi(a2, a3);
        *reinterpret_cast<uint32_t*>(Cl + base1 + nt * 8) = pack_lo_res(a2, a3);
    }
}

// ===========================================================================

extern "C" void kernel_launch(void* const* d_in, const int* in_sizes, int n_in,
                              void* d_out, int out_size)
{
    (void)in_sizes; (void)n_in; (void)out_size;
    const float* x  = (const float*)d_in[0];
    const float* wq = (const float*)d_in[1];
    const float* wk = (const float*)d_in[2];
    const float* wv = (const float*)d_in[3];
    const float* wo = (const float*)d_in[4];
    const float* rb = (const float*)d_in[5];
    float* out      = (float*)d_out;
    float* out_bias = out + (size_t)BB * SS * MD;

    __nv_bfloat16 *xh,*xl,*wqh,*wql,*wkh,*wkl,*wvh,*wvl,*woh,*wol,*ch,*cl;
    cudaGetSymbolAddress((void**)&xh,  gx_h);  cudaGetSymbolAddress((void**)&xl,  gx_l);
    cudaGetSymbolAddress((void**)&wqh, gwq_h); cudaGetSymbolAddress((void**)&wql, gwq_l);
    cudaGetSymbolAddress((void**)&wkh, gwk_h); cudaGetSymbolAddress((void**)&wkl, gwk_l);
    cudaGetSymbolAddress((void**)&wvh, gwv_h); cudaGetSymbolAddress((void**)&wvl, gwv_l);
    cudaGetSymbolAddress((void**)&woh, gwo_h); cudaGetSymbolAddress((void**)&wol, gwo_l);
    cudaGetSymbolAddress((void**)&ch,  gc_h);  cudaGetSymbolAddress((void**)&cl,  gc_l);

    cudaFuncSetAttribute(gemm_qkv, cudaFuncAttributeMaxDynamicSharedMemorySize, GSMEM_BYTES);
    cudaFuncSetAttribute(gemm_out, cudaFuncAttributeMaxDynamicSharedMemorySize, GSMEM_BYTES);
    cudaFuncSetAttribute(attn_mma, cudaFuncAttributeMaxDynamicSharedMemorySize, ASMEM_BYTES);

    // one-shot conversions + bias table
    convert_kernel<<<(MTOT*MD/8 + 255)/256, 256>>>(x,  xh,  xl,  MTOT*MD/8);
    convert_kernel<<<(MD*MD/8   + 255)/256, 256>>>(wq, wqh, wql, MD*MD/8);
    convert_kernel<<<(MD*MD/8   + 255)/256, 256>>>(wk, wkh, wkl, MD*MD/8);
    convert_kernel<<<(MD*MD/8   + 255)/256, 256>>>(wv, wvh, wvl, MD*MD/8);
    convert_kernel<<<(MD*MD/8   + 255)/256, 256>>>(wo, woh, wol, MD*MD/8);
    bias_table_kernel<<<(HH*4095 + 255)/256, 256>>>(rb);

    // fused QKV projections (2 CTAs/SM GEMM) in ONE launch
    gemm_qkv<<<1536, 256, GSMEM_BYTES>>>();

    // attention -> ctx (bf16 hi/lo) + position_bias materialization
    attn_mma<<<dim3(16, 64), 256, ASMEM_BYTES>>>(ch, cl, out_bias);

    // output projection (fp32)
    gemm_out<<<512, 256, GSMEM_BYTES>>>(out);
}

// round 13
// speedup vs baseline: 1.0985x; 1.0985x over previous
#include <cuda_runtime.h>
#include <cuda_bf16.h>
#include <cuda_fp16.h>
#include <cstdint>
#include <math.h>

#define BB 2
#define SS 2048
#define HH 32
#define HD 64
#define MD 2048
#define MTOT (BB*SS)

// ---------------- device scratch (static, no allocation) ----------------
__device__ __nv_bfloat16 gx_h[MTOT*MD],  gx_l[MTOT*MD];
__device__ __nv_bfloat16 gwq_h[MD*MD],   gwq_l[MD*MD];
__device__ __nv_bfloat16 gwk_h[MD*MD],   gwk_l[MD*MD];
__device__ __nv_bfloat16 gwv_h[MD*MD],   gwv_l[MD*MD];
__device__ __half        gwo_h[MD*MD],   gwo_l[MD*MD];     // fp16 (2-term path)
__device__ __nv_bfloat16 gq_h[MTOT*MD],  gq_l[MTOT*MD];    // [bh][s][64]
__device__ __nv_bfloat16 gk_h[MTOT*MD],  gk_l[MTOT*MD];
__device__ __half        gv_h[MTOT*MD],  gv_l[MTOT*MD];    // fp16 (PV 2-term)
__device__ __half        gc_h[MTOT*MD];                    // ctx fp16 hi only
__device__ float g_biastab[HH*4096];

// ---------------- small helpers ----------------
__device__ __forceinline__ uint32_t smem_to_u32(const void* p) {
    uint32_t a;
    asm("{ .reg .u64 t; cvta.to.shared.u64 t, %1; cvt.u32.u64 %0, t; }" : "=r"(a) : "l"(p));
    return a;
}
__device__ __forceinline__ void cp16(uint32_t dst, const void* src) {
    asm volatile("cp.async.cg.shared.global [%0], [%1], 16;" :: "r"(dst), "l"(src));
}
__device__ __forceinline__ void cp4(uint32_t dst, const void* src) {
    asm volatile("cp.async.ca.shared.global [%0], [%1], 4;" :: "r"(dst), "l"(src));
}
#define CP_COMMIT() asm volatile("cp.async.commit_group;" ::: "memory")
#define CP_WAIT(n)  asm volatile("cp.async.wait_group %0;" :: "n"(n) : "memory")

__device__ __forceinline__ void ldx4(uint32_t* r, uint32_t addr) {
    asm volatile("ldmatrix.sync.aligned.m8n8.x4.shared.b16 {%0,%1,%2,%3}, [%4];"
                 : "=r"(r[0]), "=r"(r[1]), "=r"(r[2]), "=r"(r[3]) : "r"(addr));
}
__device__ __forceinline__ void ldx4t(uint32_t* r, uint32_t addr) {
    asm volatile("ldmatrix.sync.aligned.m8n8.x4.trans.shared.b16 {%0,%1,%2,%3}, [%4];"
                 : "=r"(r[0]), "=r"(r[1]), "=r"(r[2]), "=r"(r[3]) : "r"(addr));
}
__device__ __forceinline__ void mma_bf16(float* d, const uint32_t* a,
                                         uint32_t b0, uint32_t b1) {
    asm volatile(
        "mma.sync.aligned.m16n8k16.row.col.f32.bf16.bf16.f32 "
        "{%0,%1,%2,%3}, {%4,%5,%6,%7}, {%8,%9}, {%0,%1,%2,%3};"
        : "+f"(d[0]), "+f"(d[1]), "+f"(d[2]), "+f"(d[3])
        : "r"(a[0]), "r"(a[1]), "r"(a[2]), "r"(a[3]), "r"(b0), "r"(b1));
}
__device__ __forceinline__ void mma_f16(float* d, const uint32_t* a,
                                        uint32_t b0, uint32_t b1) {
    asm volatile(
        "mma.sync.aligned.m16n8k16.row.col.f32.f16.f16.f32 "
        "{%0,%1,%2,%3}, {%4,%5,%6,%7}, {%8,%9}, {%0,%1,%2,%3};"
        : "+f"(d[0]), "+f"(d[1]), "+f"(d[2]), "+f"(d[3])
        : "r"(a[0]), "r"(a[1]), "r"(a[2]), "r"(a[3]), "r"(b0), "r"(b1));
}

__device__ __forceinline__ uint32_t pack_hi(float a, float b) {
    return __byte_perm(__float_as_uint(a), __float_as_uint(b), 0x7632);
}
__device__ __forceinline__ uint32_t pack_lo_res(float a, float b) {
    float ra = a - __uint_as_float(__float_as_uint(a) & 0xffff0000u);
    float rb = b - __uint_as_float(__float_as_uint(b) & 0xffff0000u);
    uint32_t r;
    asm("cvt.rn.bf16x2.f32 %0, %1, %2;" : "=r"(r) : "f"(rb), "f"(ra));
    return r;
}
__device__ __forceinline__ uint32_t pack_h16(float a, float b) {
    uint32_t r;
    asm("cvt.rn.f16x2.f32 %0, %1, %2;" : "=r"(r) : "f"(b), "f"(a));
    return r;
}
__device__ __forceinline__ uint32_t pack_l16(float a, float b) {
    float ra = a - __half2float(__float2half_rn(a));
    float rb = b - __half2float(__float2half_rn(b));
    uint32_t r;
    asm("cvt.rn.f16x2.f32 %0, %1, %2;" : "=r"(r) : "f"(rb), "f"(ra));
    return r;
}

// fp32 -> bf16 hi/lo split; 8 floats/thread
__global__ void convert_kernel(const float* __restrict__ in,
                               __nv_bfloat16* __restrict__ hi,
                               __nv_bfloat16* __restrict__ lo, int n8) {
    int i = blockIdx.x * blockDim.x + threadIdx.x;
    if (i >= n8) return;
    float4 f0 = reinterpret_cast<const float4*>(in)[2*i];
    float4 f1 = reinterpret_cast<const float4*>(in)[2*i + 1];
    reinterpret_cast<uint4*>(hi)[i] = make_uint4(
        pack_hi(f0.x, f0.y), pack_hi(f0.z, f0.w),
        pack_hi(f1.x, f1.y), pack_hi(f1.z, f1.w));
    reinterpret_cast<uint4*>(lo)[i] = make_uint4(
        pack_lo_res(f0.x, f0.y), pack_lo_res(f0.z, f0.w),
        pack_lo_res(f1.x, f1.y), pack_lo_res(f1.z, f1.w));
}
// fp32 -> fp16 hi/lo split; 8 floats/thread
__global__ void convert_f16_kernel(const float* __restrict__ in,
                                   __half* __restrict__ hi,
                                   __half* __restrict__ lo, int n8) {
    int i = blockIdx.x * blockDim.x + threadIdx.x;
    if (i >= n8) return;
    float4 f0 = reinterpret_cast<const float4*>(in)[2*i];
    float4 f1 = reinterpret_cast<const float4*>(in)[2*i + 1];
    reinterpret_cast<uint4*>(hi)[i] = make_uint4(
        pack_h16(f0.x, f0.y), pack_h16(f0.z, f0.w),
        pack_h16(f1.x, f1.y), pack_h16(f1.z, f1.w));
    reinterpret_cast<uint4*>(lo)[i] = make_uint4(
        pack_l16(f0.x, f0.y), pack_l16(f0.z, f0.w),
        pack_l16(f1.x, f1.y), pack_l16(f1.z, f1.w));
}

// 256-thread loader (attention KV, 128B rows): thread = (row t>>1, half t&1)
__device__ __forceinline__ void issue4(uint32_t sb,
    const void* s0v, const void* s1v, const void* s2v, const void* s3v, int tid)
{
    const char* s0 = (const char*)s0v; const char* s1 = (const char*)s1v;
    const char* s2 = (const char*)s2v; const char* s3 = (const char*)s3v;
    const int r2 = tid >> 1, hf = tid & 1;
    const uint32_t dd = (uint32_t)(r2 * 128 + hf * 64);
    #pragma unroll
    for (int i = 0; i < 4; i++) {
        uint32_t o = dd + i * 16; o ^= (o >> 3) & 0x70;
        cp16(sb + o,         s0 + i * 16);
        cp16(sb + 16384 + o, s1 + i * 16);
        cp16(sb + 32768 + o, s2 + i * 16);
        cp16(sb + 49152 + o, s3 + i * 16);
    }
}

// ===========================================================================
// bf16x3 GEMM: 256 threads / 8 warps (4m x 2n), warp tile 32x64,
// 128x128 CTA tile, K-chunk 32, 3-stage pipeline (96KB) -> 2 CTAs/SM.
// stage layout: Ah 8K | Al 8K | Bh 8K | Bl 8K = 32K
// ===========================================================================
#define GSTAGE 32768
#define GSMEM_BYTES (3 * GSTAGE)

struct GemmCtx {
    uint32_t su;
    int tid, l, w, wm, wn, grp, lr;
    uint32_t a_row[2], b_row[4], a_c16, b_c16;
};

__device__ __forceinline__ void gemm_init(GemmCtx& g, char* smem) {
    g.su = smem_to_u32(smem);
    g.tid = threadIdx.x;
    g.l = g.tid & 31; g.w = g.tid >> 5;
    g.wm = g.w >> 1;  g.wn = g.w & 1;          // 4m x 2n warp grid
    g.grp = g.l >> 3; g.lr = g.l & 7;
    #pragma unroll
    for (int mt = 0; mt < 2; mt++)
        g.a_row[mt] = (uint32_t)((g.wm * 32 + mt * 16 + g.lr + (g.grp & 1) * 8) * 64);
    #pragma unroll
    for (int j = 0; j < 4; j++)
        g.b_row[j] = (uint32_t)((g.wn * 64 + j * 16 + g.lr + (g.grp >> 1) * 8) * 64);
    g.a_c16 = (uint32_t)(g.grp >> 1) * 16;
    g.b_c16 = (uint32_t)(g.grp & 1) * 16;
}

__device__ __forceinline__ void issue_g(uint32_t sb,
    const __nv_bfloat16* a_h, const __nv_bfloat16* a_l,
    const __nv_bfloat16* b_h, const __nv_bfloat16* b_l, int tid)
{
    uint32_t o = (uint32_t)((tid >> 1) * 64 + (tid & 1) * 32);
    uint32_t o0 = o ^ ((o >> 3) & 0x30);
    uint32_t o1 = o0 ^ 16;
    cp16(sb + o0,         a_h);     cp16(sb + o1,         a_h + 8);
    cp16(sb + 8192  + o0, a_l);     cp16(sb + 8192  + o1, a_l + 8);
    cp16(sb + 16384 + o0, b_h);     cp16(sb + 16384 + o1, b_h + 8);
    cp16(sb + 24576 + o0, b_l);     cp16(sb + 24576 + o1, b_l + 8);
}

__device__ __forceinline__ void gemm_body(
    GemmCtx& g,
    const __nv_bfloat16* pa_h, const __nv_bfloat16* pa_l,
    const __nv_bfloat16* pb_h, const __nv_bfloat16* pb_l,
    float acc[2][8][4])
{
    issue_g(g.su,          pa_h,      pa_l,      pb_h,      pb_l,      g.tid); CP_COMMIT();
    issue_g(g.su + GSTAGE, pa_h + 32, pa_l + 32, pb_h + 32, pb_l + 32, g.tid); CP_COMMIT();

    for (int c = 0; c < 64; c++) {
        CP_WAIT(1);
        __syncthreads();
        if (c + 2 < 64) {
            int k0 = (c + 2) * 32;
            issue_g(g.su + (uint32_t)((c + 2) % 3) * GSTAGE,
                    pa_h + k0, pa_l + k0, pb_h + k0, pb_l + k0, g.tid);
        }
        CP_COMMIT();

        const uint32_t cur = g.su + (uint32_t)(c % 3) * GSTAGE;

        #pragma unroll
        for (int ks = 0; ks < 2; ks++) {
            uint32_t ah[2][4], al[2][4];
            #pragma unroll
            for (int mt = 0; mt < 2; mt++) {
                uint32_t off = g.a_row[mt] + (uint32_t)(ks * 32) + g.a_c16;
                off ^= (off >> 3) & 0x30;
                ldx4(ah[mt], cur + off);
                ldx4(al[mt], cur + 8192 + off);
            }
            #pragma unroll
            for (int jp = 0; jp < 2; jp++) {
                uint32_t bh[2][4], bl[2][4];
                #pragma unroll
                for (int u = 0; u < 2; u++) {
                    uint32_t off = g.b_row[2*jp + u] + (uint32_t)(ks * 32) + g.b_c16;
                    off ^= (off >> 3) & 0x30;
                    ldx4(bh[u], cur + 16384 + off);
                    ldx4(bl[u], cur + 24576 + off);
                }
                #pragma unroll
                for (int u = 0; u < 2; u++)
                    #pragma unroll
                    for (int mt = 0; mt < 2; mt++) {
                        mma_bf16(acc[mt][4*jp + 2*u],     ah[mt], bh[u][0], bh[u][1]);
                        mma_bf16(acc[mt][4*jp + 2*u + 1], ah[mt], bh[u][2], bh[u][3]);
                    }
                #pragma unroll
                for (int u = 0; u < 2; u++)
                    #pragma unroll
                    for (int mt = 0; mt < 2; mt++) {
                        mma_bf16(acc[mt][4*jp + 2*u],     ah[mt], bl[u][0], bl[u][1]);
                        mma_bf16(acc[mt][4*jp + 2*u + 1], ah[mt], bl[u][2], bl[u][3]);
                    }
                #pragma unroll
                for (int u = 0; u < 2; u++)
                    #pragma unroll
                    for (int mt = 0; mt < 2; mt++) {
                        mma_bf16(acc[mt][4*jp + 2*u],     al[mt], bh[u][0], bh[u][1]);
                        mma_bf16(acc[mt][4*jp + 2*u + 1], al[mt], bh[u][2], bh[u][3]);
                    }
            }
        }
    }
}

// ---- fused QKV: grid 1536 = 3 x 512 tiles. wsel 0/1 -> bf16 q/k out;
// ---- wsel 2 -> v stored as fp16 hi/lo (value path is fp16 2-term later).
__global__ void __launch_bounds__(256, 2) gemm_qkv()
{
    extern __shared__ char smem[];
    GemmCtx g; gemm_init(g, smem);

    const int wsel = blockIdx.x >> 9;
    const int tile = blockIdx.x & 511;
    const int m0 = (tile >> 4) * 128, n0 = (tile & 15) * 128;

    const __nv_bfloat16 *Bh, *Bl;
    if (wsel == 0)      { Bh = gwq_h; Bl = gwq_l; }
    else if (wsel == 1) { Bh = gwk_h; Bl = gwk_l; }
    else                { Bh = gwv_h; Bl = gwv_l; }

    const int sr = g.tid >> 1, sc = (g.tid & 1) * 16;
    const __nv_bfloat16* pa_h = gx_h + (size_t)(m0 + sr) * 2048 + sc;
    const __nv_bfloat16* pa_l = gx_l + (size_t)(m0 + sr) * 2048 + sc;
    const __nv_bfloat16* pb_h = Bh   + (size_t)(n0 + sr) * 2048 + sc;
    const __nv_bfloat16* pb_l = Bl   + (size_t)(n0 + sr) * 2048 + sc;

    float acc[2][8][4];
    #pragma unroll
    for (int mt = 0; mt < 2; mt++)
        #pragma unroll
        for (int nt = 0; nt < 8; nt++)
            #pragma unroll
            for (int i = 0; i < 4; i++) acc[mt][nt][i] = 0.f;

    gemm_body(g, pa_h, pa_l, pb_h, pb_l, acc);

    #pragma unroll
    for (int mt = 0; mt < 2; mt++) {
        #pragma unroll
        for (int nt = 0; nt < 8; nt++) {
            int r  = m0 + g.wm * 32 + mt * 16 + (g.l >> 2);
            int cc = n0 + g.wn * 64 + nt * 8 + 2 * (g.l & 3);
            int b = r >> 11, s = r & 2047, h = cc >> 6, d = cc & 63;
            size_t base = (((size_t)(b * 32 + h)) * 2048 + s) * 64 + d;
            if (wsel == 2) {
                *reinterpret_cast<uint32_t*>(gv_h + base) =
                    pack_h16(acc[mt][nt][0], acc[mt][nt][1]);
                *reinterpret_cast<uint32_t*>(gv_l + base) =
                    pack_l16(acc[mt][nt][0], acc[mt][nt][1]);
                *reinterpret_cast<uint32_t*>(gv_h + base + 8 * 64) =
                    pack_h16(acc[mt][nt][2], acc[mt][nt][3]);
                *reinterpret_cast<uint32_t*>(gv_l + base + 8 * 64) =
                    pack_l16(acc[mt][nt][2], acc[mt][nt][3]);
            } else {
                __nv_bfloat16* Ch = (wsel == 0) ? gq_h : gk_h;
                __nv_bfloat16* Cl = (wsel == 0) ? gq_l : gk_l;
                *reinterpret_cast<uint32_t*>(Ch + base) =
                    pack_hi(acc[mt][nt][0], acc[mt][nt][1]);
                *reinterpret_cast<uint32_t*>(Cl + base) =
                    pack_lo_res(acc[mt][nt][0], acc[mt][nt][1]);
                *reinterpret_cast<uint32_t*>(Ch + base + 8 * 64) =
                    pack_hi(acc[mt][nt][2], acc[mt][nt][3]);
                *reinterpret_cast<uint32_t*>(Cl + base + 8 * 64) =
                    pack_lo_res(acc[mt][nt][2], acc[mt][nt][3]);
            }
        }
    }
}

// ===========================================================================
// fp16 2-term out-projection: out = ctx_h @ (wo_h + wo_l)^T, fp32 C.
// stage: Ah 8K | Bh 8K | Bl 8K = 24K, 3 stages = 72KB, 2 CTAs/SM.
// ===========================================================================
#define OSTAGE 24576
#define OSMEM_BYTES (3 * OSTAGE)

__device__ __forceinline__ void issue_o(uint32_t sb,
    const __half* a_h, const __half* b_h, const __half* b_l, int tid)
{
    uint32_t o = (uint32_t)((tid >> 1) * 64 + (tid & 1) * 32);
    uint32_t o0 = o ^ ((o >> 3) & 0x30);
    uint32_t o1 = o0 ^ 16;
    cp16(sb + o0,         a_h);     cp16(sb + o1,         a_h + 8);
    cp16(sb + 8192  + o0, b_h);     cp16(sb + 8192  + o1, b_h + 8);
    cp16(sb + 16384 + o0, b_l);     cp16(sb + 16384 + o1, b_l + 8);
}

__global__ void __launch_bounds__(256, 2) gemm_out(float* __restrict__ Cf)
{
    extern __shared__ char smem[];
    GemmCtx g; gemm_init(g, smem);
    const int m0 = (blockIdx.x >> 4) * 128, n0 = (blockIdx.x & 15) * 128;

    const int sr = g.tid >> 1, sc = (g.tid & 1) * 16;
    const __half* pa_h = gc_h  + (size_t)(m0 + sr) * 2048 + sc;
    const __half* pb_h = gwo_h + (size_t)(n0 + sr) * 2048 + sc;
    const __half* pb_l = gwo_l + (size_t)(n0 + sr) * 2048 + sc;

    float acc[2][8][4];
    #pragma unroll
    for (int mt = 0; mt < 2; mt++)
        #pragma unroll
        for (int nt = 0; nt < 8; nt++)
            #pragma unroll
            for (int i = 0; i < 4; i++) acc[mt][nt][i] = 0.f;

    issue_o(g.su,          pa_h,      pb_h,      pb_l,      g.tid); CP_COMMIT();
    issue_o(g.su + OSTAGE, pa_h + 32, pb_h + 32, pb_l + 32, g.tid); CP_COMMIT();

    for (int c = 0; c < 64; c++) {
        CP_WAIT(1);
        __syncthreads();
        if (c + 2 < 64) {
            int k0 = (c + 2) * 32;
            issue_o(g.su + (uint32_t)((c + 2) % 3) * OSTAGE,
                    pa_h + k0, pb_h + k0, pb_l + k0, g.tid);
        }
        CP_COMMIT();

        const uint32_t cur = g.su + (uint32_t)(c % 3) * OSTAGE;

        #pragma unroll
        for (int ks = 0; ks < 2; ks++) {
            uint32_t ah[2][4];
            #pragma unroll
            for (int mt = 0; mt < 2; mt++) {
                uint32_t off = g.a_row[mt] + (uint32_t)(ks * 32) + g.a_c16;
                off ^= (off >> 3) & 0x30;
                ldx4(ah[mt], cur + off);
            }
            #pragma unroll
            for (int jp = 0; jp < 2; jp++) {
                uint32_t bh[2][4], bl[2][4];
                #pragma unroll
                for (int u = 0; u < 2; u++) {
                    uint32_t off = g.b_row[2*jp + u] + (uint32_t)(ks * 32) + g.b_c16;
                    off ^= (off >> 3) & 0x30;
                    ldx4(bh[u], cur + 8192  + off);
                    ldx4(bl[u], cur + 16384 + off);
                }
                #pragma unroll
                for (int u = 0; u < 2; u++)
                    #pragma unroll
                    for (int mt = 0; mt < 2; mt++) {
                        mma_f16(acc[mt][4*jp + 2*u],     ah[mt], bh[u][0], bh[u][1]);
                        mma_f16(acc[mt][4*jp + 2*u + 1], ah[mt], bh[u][2], bh[u][3]);
                    }
                #pragma unroll
                for (int u = 0; u < 2; u++)
                    #pragma unroll
                    for (int mt = 0; mt < 2; mt++) {
                        mma_f16(acc[mt][4*jp + 2*u],     ah[mt], bl[u][0], bl[u][1]);
                        mma_f16(acc[mt][4*jp + 2*u + 1], ah[mt], bl[u][2], bl[u][3]);
                    }
            }
        }
    }

    #pragma unroll
    for (int mt = 0; mt < 2; mt++) {
        #pragma unroll
        for (int nt = 0; nt < 8; nt++) {
            int r  = m0 + g.wm * 32 + mt * 16 + (g.l >> 2);
            int cc = n0 + g.wn * 64 + nt * 8 + 2 * (g.l & 3);
            *reinterpret_cast<float2*>(Cf + (size_t)r * 2048 + cc) =
                make_float2(acc[mt][nt][0], acc[mt][nt][1]);
            *reinterpret_cast<float2*>(Cf + (size_t)(r + 8) * 2048 + cc) =
                make_float2(acc[mt][nt][2], acc[mt][nt][3]);
        }
    }
}

// ===========================================================================
// relative-position bucket (exact integer T5 formula) + bias table
// ===========================================================================
__device__ __forceinline__ int rel_bucket(int dist) {
    int rel = dist > 0 ? 16 : 0;
    int d = abs(dist);
    int sb;
    if (d < 8)       sb = d;
    else if (d < 12) sb = 8;
    else if (d < 16) sb = 9;
    else if (d < 23) sb = 10;
    else if (d < 32) sb = 11;
    else if (d < 46) sb = 12;
    else if (d < 64) sb = 13;
    else if (d < 91) sb = 14;
    else             sb = 15;
    return rel + sb;
}

__global__ void bias_table_kernel(const float* __restrict__ rel_bias) {
    int idx = blockIdx.x * blockDim.x + threadIdx.x;
    if (idx >= HH * 4095) return;
    int h = idx / 4095;
    int di = idx % 4095;
    g_biastab[h * 4096 + di] = rel_bias[rel_bucket(di - 2047) * HH + h];
}

// ===========================================================================
// FA2-style attention: QK bf16x3 (score path), PV fp16 2-term (value path).
// KV tile 128 (16 iters) + folded bias write. ctx stored fp16 hi only.
// smem: Qh 16K | Ql 16K | 2 x { Kh Kl Vh Vl } 64K | 2 x bias 1K = 162K
// ===========================================================================
#define ASMEM_BYTES (32768 + 2*65536 + 2*1024)

__global__ void __launch_bounds__(256, 1) attn_mma(float* __restrict__ out_bias)
{
    extern __shared__ char smem[];
    const uint32_t su = smem_to_u32(smem);
    const int tid = threadIdx.x, l = tid & 31, w = tid >> 5;
    const int grp = l >> 3, lr = l & 7;
    const int bh = blockIdx.y, h = bh & 31, b = bh >> 5;
    const int q0 = blockIdx.x * 128;
    const size_t bhoff = (size_t)bh * SS * HD;
    const int r2 = tid >> 1, hf = tid & 1;

    // Q tiles -> smem (part of group 0)
    {
        const __nv_bfloat16* sh = gq_h + bhoff + (size_t)(q0 + r2) * 64 + hf * 32;
        const __nv_bfloat16* sl = gq_l + bhoff + (size_t)(q0 + r2) * 64 + hf * 32;
        uint32_t dd = (uint32_t)(r2 * 128 + hf * 64);
        #pragma unroll
        for (int i = 0; i < 4; i++) {
            uint32_t o = dd + i * 16; o ^= (o >> 3) & 0x70;
            cp16(su + o,         sh + i * 8);
            cp16(su + 16384 + o, sl + i * 8);
        }
    }

    // KV + bias issue for ktile kt
    auto issue_kv = [&](int kt) {
        uint32_t sb = su + 32768 + (uint32_t)(kt & 1) * 65536;
        size_t off = bhoff + (size_t)(kt * 128 + r2) * 64 + hf * 32;
        issue4(sb, gk_h + off, gk_l + off, gv_h + off, gv_l + off, tid);
        int w0 = kt * 128 - q0 + 1920;
        cp4(su + 163840 + (uint32_t)(kt & 1) * 1024 + tid * 4,
            &g_biastab[h * 4096 + w0 + tid]);
    };
    issue_kv(0); CP_COMMIT();
    issue_kv(1); CP_COMMIT();

    float o[8][4];
    #pragma unroll
    for (int nt = 0; nt < 8; nt++)
        #pragma unroll
        for (int i = 0; i < 4; i++) o[nt][i] = 0.f;
    float mrow[2] = {-1e30f, -1e30f};
    float lrow[2] = {0.f, 0.f};

    const uint32_t qbase  = (uint32_t)((w * 16 + lr + (grp & 1) * 8) * 128 + (grp >> 1) * 16);
    const uint32_t kvbase = (uint32_t)((lr + (grp >> 1) * 8) * 128 + (grp & 1) * 16);

    for (int kt = 0; kt < 16; kt++) {
        CP_WAIT(1);
        __syncthreads();
        const uint32_t SB = su + 32768 + (uint32_t)(kt & 1) * 65536;
        const float* bsm = reinterpret_cast<const float*>(smem + 163840 + (kt & 1) * 1024);

        // ---- S = Q K^T (bf16x3) ----
        float s[16][4];
        #pragma unroll
        for (int j = 0; j < 16; j++)
            #pragma unroll
            for (int i = 0; i < 4; i++) s[j][i] = 0.f;

        #pragma unroll
        for (int ks = 0; ks < 4; ks++) {
            uint32_t qo = qbase + (uint32_t)(ks * 32); qo ^= (qo >> 3) & 0x70;
            uint32_t ah[4], al[4];
            ldx4(ah, su + qo);
            ldx4(al, su + 16384 + qo);
            #pragma unroll
            for (int jp = 0; jp < 4; jp++) {
                uint32_t kh[2][4], kl[2][4];
                #pragma unroll
                for (int u = 0; u < 2; u++) {
                    uint32_t ko = kvbase + (uint32_t)((2*jp + u) * 2048 + ks * 32);
                    ko ^= (ko >> 3) & 0x70;
                    ldx4(kh[u], SB + ko);
                    ldx4(kl[u], SB + 16384 + ko);
                }
                #pragma unroll
                for (int u = 0; u < 2; u++) {
                    mma_bf16(s[4*jp + 2*u],     ah, kh[u][0], kh[u][1]);
                    mma_bf16(s[4*jp + 2*u + 1], ah, kh[u][2], kh[u][3]);
                }
                #pragma unroll
                for (int u = 0; u < 2; u++) {
                    mma_bf16(s[4*jp + 2*u],     ah, kl[u][0], kl[u][1]);
                    mma_bf16(s[4*jp + 2*u + 1], ah, kl[u][2], kl[u][3]);
                }
                #pragma unroll
                for (int u = 0; u < 2; u++) {
                    mma_bf16(s[4*jp + 2*u],     al, kh[u][0], kh[u][1]);
                    mma_bf16(s[4*jp + 2*u + 1], al, kh[u][2], kh[u][3]);
                }
            }
        }

        // ---- bias + online softmax ----
        const int bb = 127 - (w * 16 + (l >> 2)) + 2 * (l & 3);
        #pragma unroll
        for (int j = 0; j < 16; j++) {
            s[j][0] += bsm[bb + 8*j];
            s[j][1] += bsm[bb + 8*j + 1];
            s[j][2] += bsm[bb + 8*j - 8];
            s[j][3] += bsm[bb + 8*j - 7];
        }
        #pragma unroll
        for (int u = 0; u < 2; u++) {
            float mx = -1e30f;
            #pragma unroll
            for (int j = 0; j < 16; j++)
                mx = fmaxf(mx, fmaxf(s[j][2*u], s[j][2*u+1]));
            mx = fmaxf(mx, __shfl_xor_sync(0xffffffffu, mx, 1));
            mx = fmaxf(mx, __shfl_xor_sync(0xffffffffu, mx, 2));
            float mnew = fmaxf(mrow[u], mx);
            float scale = __expf(mrow[u] - mnew);
            mrow[u] = mnew;
            float sum = 0.f;
            #pragma unroll
            for (int j = 0; j < 16; j++) {
                float p0 = __expf(s[j][2*u]   - mnew);
                float p1 = __expf(s[j][2*u+1] - mnew);
                s[j][2*u] = p0; s[j][2*u+1] = p1;
                sum += p0 + p1;
            }
            sum += __shfl_xor_sync(0xffffffffu, sum, 1);
            sum += __shfl_xor_sync(0xffffffffu, sum, 2);
            lrow[u] = lrow[u] * scale + sum;
            #pragma unroll
            for (int nt = 0; nt < 8; nt++) {
                o[nt][2*u]   *= scale;
                o[nt][2*u+1] *= scale;
            }
        }

        // ---- O += P V (fp16 2-term: P fp16-hi, V fp16 hi+lo) ----
        #pragma unroll
        for (int ks = 0; ks < 8; ks++) {
            uint32_t aph[4];
            aph[0] = pack_h16(s[2*ks][0],   s[2*ks][1]);
            aph[1] = pack_h16(s[2*ks][2],   s[2*ks][3]);
            aph[2] = pack_h16(s[2*ks+1][0], s[2*ks+1][1]);
            aph[3] = pack_h16(s[2*ks+1][2], s[2*ks+1][3]);
            #pragma unroll
            for (int dp = 0; dp < 2; dp++) {
                uint32_t vh[2][4], vl[2][4];
                #pragma unroll
                for (int u = 0; u < 2; u++) {
                    uint32_t vo = kvbase + (uint32_t)(ks * 2048 + (2*dp + u) * 32);
                    vo ^= (vo >> 3) & 0x70;
                    ldx4t(vh[u], SB + 32768 + vo);
                    ldx4t(vl[u], SB + 49152 + vo);
                }
                #pragma unroll
                for (int u = 0; u < 2; u++) {
                    mma_f16(o[4*dp + 2*u],     aph, vh[u][0], vh[u][2]);
                    mma_f16(o[4*dp + 2*u + 1], aph, vh[u][1], vh[u][3]);
                }
                #pragma unroll
                for (int u = 0; u < 2; u++) {
                    mma_f16(o[4*dp + 2*u],     aph, vl[u][0], vl[u][2]);
                    mma_f16(o[4*dp + 2*u + 1], aph, vl[u][1], vl[u][3]);
                }
            }
        }

        // ---- folded position_bias materialization (b==0 CTAs only) ----
        if (b == 0) {
            const int q = tid >> 1;          // 0..127
            const int kh2 = (tid & 1) * 64;  // 0 or 64
            float* dst = out_bias + ((size_t)h * 2048 + (q0 + q)) * 2048
                                  + kt * 128 + kh2;
            const int bidx = kh2 - q + 127;
            #pragma unroll
            for (int i = 0; i < 16; i++) {
                *reinterpret_cast<float4*>(dst + 4*i) =
                    make_float4(bsm[bidx + 4*i],     bsm[bidx + 4*i + 1],
                                bsm[bidx + 4*i + 2], bsm[bidx + 4*i + 3]);
            }
        }

        __syncthreads();
        if (kt + 2 < 16) issue_kv(kt + 2);
        CP_COMMIT();
    }

    // ---- epilogue: normalize, fp16-hi store of ctx ----
    const float inv0 = 1.f / lrow[0], inv1 = 1.f / lrow[1];
    const int rg0 = b * 2048 + q0 + w * 16 + (l >> 2);
    const size_t base0 = (size_t)rg0 * 2048 + h * 64 + 2 * (l & 3);
    const size_t base1 = base0 + (size_t)8 * 2048;
    #pragma unroll
    for (int nt = 0; nt < 8; nt++) {
        float a0 = o[nt][0] * inv0, a1 = o[nt][1] * inv0;
        float a2 = o[nt][2] * inv1, a3 = o[nt][3] * inv1;
        *reinterpret_cast<uint32_t*>(gc_h + base0 + nt * 8) = pack_h16(a0, a1);
        *reinterpret_cast<uint32_t*>(gc_h + base1 + nt * 8) = pack_h16(a2, a3);
    }
}

// ===========================================================================

extern "C" void kernel_launch(void* const* d_in, const int* in_sizes, int n_in,
                              void* d_out, int out_size)
{
    (void)in_sizes; (void)n_in; (void)out_size;
    const float* x  = (const float*)d_in[0];
    const float* wq = (const float*)d_in[1];
    const float* wk = (const float*)d_in[2];
    const float* wv = (const float*)d_in[3];
    const float* wo = (const float*)d_in[4];
    const float* rb = (const float*)d_in[5];
    float* out      = (float*)d_out;
    float* out_bias = out + (size_t)BB * SS * MD;

    __nv_bfloat16 *xh,*xl,*wqh,*wql,*wkh,*wkl,*wvh,*wvl;
    __half *woh,*wol;
    cudaGetSymbolAddress((void**)&xh,  gx_h);  cudaGetSymbolAddress((void**)&xl,  gx_l);
    cudaGetSymbolAddress((void**)&wqh, gwq_h); cudaGetSymbolAddress((void**)&wql, gwq_l);
    cudaGetSymbolAddress((void**)&wkh, gwk_h); cudaGetSymbolAddress((void**)&wkl, gwk_l);
    cudaGetSymbolAddress((void**)&wvh, gwv_h); cudaGetSymbolAddress((void**)&wvl, gwv_l);
    cudaGetSymbolAddress((void**)&woh, gwo_h); cudaGetSymbolAddress((void**)&wol, gwo_l);

    cudaFuncSetAttribute(gemm_qkv, cudaFuncAttributeMaxDynamicSharedMemorySize, GSMEM_BYTES);
    cudaFuncSetAttribute(gemm_out, cudaFuncAttributeMaxDynamicSharedMemorySize, OSMEM_BYTES);
    cudaFuncSetAttribute(attn_mma, cudaFuncAttributeMaxDynamicSharedMemorySize, ASMEM_BYTES);

    // one-shot conversions + bias table
    convert_kernel<<<(MTOT*MD/8 + 255)/256, 256>>>(x,  xh,  xl,  MTOT*MD/8);
    convert_kernel<<<(MD*MD/8   + 255)/256, 256>>>(wq, wqh, wql, MD*MD/8);
    convert_kernel<<<(MD*MD/8   + 255)/256, 256>>>(wk, wkh, wkl, MD*MD/8);
    convert_kernel<<<(MD*MD/8   + 255)/256, 256>>>(wv, wvh, wvl, MD*MD/8);
    convert_f16_kernel<<<(MD*MD/8 + 255)/256, 256>>>(wo, woh, wol, MD*MD/8);
    bias_table_kernel<<<(HH*4095 + 255)/256, 256>>>(rb);

    // fused QKV projections (bf16x3; V epilogue stores fp16 hi/lo)
    gemm_qkv<<<1536, 256, GSMEM_BYTES>>>();

    // attention (QK bf16x3, PV fp16 2-term) + position_bias materialization
    attn_mma<<<dim3(16, 64), 256, ASMEM_BYTES>>>(out_bias);

    // output projection (fp16 2-term, fp32 out)
    gemm_out<<<512, 256, OSMEM_BYTES>>>(out);
}

// round 14
// speedup vs baseline: 1.2205x; 1.1111x over previous
#include <cuda_runtime.h>
#include <cuda_bf16.h>
#include <cuda_fp16.h>
#include <cstdint>
#include <math.h>

#define BB 2
#define SS 2048
#define HH 32
#define HD 64
#define MD 2048
#define MTOT (BB*SS)

// ---------------- device scratch (static, no allocation) ----------------
__device__ __nv_bfloat16 gx_h[MTOT*MD],  gx_l[MTOT*MD];
__device__ __half        gx16[MTOT*MD];                    // x fp16 (V path)
__device__ __nv_bfloat16 gwq_h[MD*MD],   gwq_l[MD*MD];
__device__ __nv_bfloat16 gwk_h[MD*MD],   gwk_l[MD*MD];
__device__ __half        gwv_h[MD*MD],   gwv_l[MD*MD];     // fp16 (2-term)
__device__ __half        gwo_h[MD*MD],   gwo_l[MD*MD];     // fp16 (2-term)
__device__ __nv_bfloat16 gq_h[MTOT*MD],  gq_l[MTOT*MD];    // [bh][s][64]
__device__ __nv_bfloat16 gk_h[MTOT*MD],  gk_l[MTOT*MD];
__device__ __half        gv16[MTOT*MD];                    // v fp16-hi only
__device__ __half        gc_h[MTOT*MD];                    // ctx fp16-hi only
__device__ float g_biastab[HH*4096];

// ---------------- small helpers ----------------
__device__ __forceinline__ uint32_t smem_to_u32(const void* p) {
    uint32_t a;
    asm("{ .reg .u64 t; cvta.to.shared.u64 t, %1; cvt.u32.u64 %0, t; }" : "=r"(a) : "l"(p));
    return a;
}
__device__ __forceinline__ void cp16(uint32_t dst, const void* src) {
    asm volatile("cp.async.cg.shared.global [%0], [%1], 16;" :: "r"(dst), "l"(src));
}
__device__ __forceinline__ void cp4(uint32_t dst, const void* src) {
    asm volatile("cp.async.ca.shared.global [%0], [%1], 4;" :: "r"(dst), "l"(src));
}
#define CP_COMMIT() asm volatile("cp.async.commit_group;" ::: "memory")
#define CP_WAIT(n)  asm volatile("cp.async.wait_group %0;" :: "n"(n) : "memory")

__device__ __forceinline__ void ldx4(uint32_t* r, uint32_t addr) {
    asm volatile("ldmatrix.sync.aligned.m8n8.x4.shared.b16 {%0,%1,%2,%3}, [%4];"
                 : "=r"(r[0]), "=r"(r[1]), "=r"(r[2]), "=r"(r[3]) : "r"(addr));
}
__device__ __forceinline__ void ldx4t(uint32_t* r, uint32_t addr) {
    asm volatile("ldmatrix.sync.aligned.m8n8.x4.trans.shared.b16 {%0,%1,%2,%3}, [%4];"
                 : "=r"(r[0]), "=r"(r[1]), "=r"(r[2]), "=r"(r[3]) : "r"(addr));
}
__device__ __forceinline__ void mma_bf16(float* d, const uint32_t* a,
                                         uint32_t b0, uint32_t b1) {
    asm volatile(
        "mma.sync.aligned.m16n8k16.row.col.f32.bf16.bf16.f32 "
        "{%0,%1,%2,%3}, {%4,%5,%6,%7}, {%8,%9}, {%0,%1,%2,%3};"
        : "+f"(d[0]), "+f"(d[1]), "+f"(d[2]), "+f"(d[3])
        : "r"(a[0]), "r"(a[1]), "r"(a[2]), "r"(a[3]), "r"(b0), "r"(b1));
}
__device__ __forceinline__ void mma_f16(float* d, const uint32_t* a,
                                        uint32_t b0, uint32_t b1) {
    asm volatile(
        "mma.sync.aligned.m16n8k16.row.col.f32.f16.f16.f32 "
        "{%0,%1,%2,%3}, {%4,%5,%6,%7}, {%8,%9}, {%0,%1,%2,%3};"
        : "+f"(d[0]), "+f"(d[1]), "+f"(d[2]), "+f"(d[3])
        : "r"(a[0]), "r"(a[1]), "r"(a[2]), "r"(a[3]), "r"(b0), "r"(b1));
}

__device__ __forceinline__ uint32_t pack_hi(float a, float b) {
    return __byte_perm(__float_as_uint(a), __float_as_uint(b), 0x7632);
}
__device__ __forceinline__ uint32_t pack_lo_res(float a, float b) {
    float ra = a - __uint_as_float(__float_as_uint(a) & 0xffff0000u);
    float rb = b - __uint_as_float(__float_as_uint(b) & 0xffff0000u);
    uint32_t r;
    asm("cvt.rn.bf16x2.f32 %0, %1, %2;" : "=r"(r) : "f"(rb), "f"(ra));
    return r;
}
__device__ __forceinline__ uint32_t pack_h16(float a, float b) {
    uint32_t r;
    asm("cvt.rn.f16x2.f32 %0, %1, %2;" : "=r"(r) : "f"(b), "f"(a));
    return r;
}
__device__ __forceinline__ uint32_t pack_l16(float a, float b) {
    float ra = a - __half2float(__float2half_rn(a));
    float rb = b - __half2float(__float2half_rn(b));
    uint32_t r;
    asm("cvt.rn.f16x2.f32 %0, %1, %2;" : "=r"(r) : "f"(rb), "f"(ra));
    return r;
}

// x -> bf16 hi/lo + fp16 single, one pass
__global__ void convert_x_kernel(const float* __restrict__ in, int n8) {
    int i = blockIdx.x * blockDim.x + threadIdx.x;
    if (i >= n8) return;
    float4 f0 = reinterpret_cast<const float4*>(in)[2*i];
    float4 f1 = reinterpret_cast<const float4*>(in)[2*i + 1];
    reinterpret_cast<uint4*>(gx_h)[i] = make_uint4(
        pack_hi(f0.x, f0.y), pack_hi(f0.z, f0.w),
        pack_hi(f1.x, f1.y), pack_hi(f1.z, f1.w));
    reinterpret_cast<uint4*>(gx_l)[i] = make_uint4(
        pack_lo_res(f0.x, f0.y), pack_lo_res(f0.z, f0.w),
        pack_lo_res(f1.x, f1.y), pack_lo_res(f1.z, f1.w));
    reinterpret_cast<uint4*>(gx16)[i] = make_uint4(
        pack_h16(f0.x, f0.y), pack_h16(f0.z, f0.w),
        pack_h16(f1.x, f1.y), pack_h16(f1.z, f1.w));
}
// fp32 -> bf16 hi/lo
__global__ void convert_kernel(const float* __restrict__ in,
                               __nv_bfloat16* __restrict__ hi,
                               __nv_bfloat16* __restrict__ lo, int n8) {
    int i = blockIdx.x * blockDim.x + threadIdx.x;
    if (i >= n8) return;
    float4 f0 = reinterpret_cast<const float4*>(in)[2*i];
    float4 f1 = reinterpret_cast<const float4*>(in)[2*i + 1];
    reinterpret_cast<uint4*>(hi)[i] = make_uint4(
        pack_hi(f0.x, f0.y), pack_hi(f0.z, f0.w),
        pack_hi(f1.x, f1.y), pack_hi(f1.z, f1.w));
    reinterpret_cast<uint4*>(lo)[i] = make_uint4(
        pack_lo_res(f0.x, f0.y), pack_lo_res(f0.z, f0.w),
        pack_lo_res(f1.x, f1.y), pack_lo_res(f1.z, f1.w));
}
// fp32 -> fp16 hi/lo
__global__ void convert_f16_kernel(const float* __restrict__ in,
                                   __half* __restrict__ hi,
                                   __half* __restrict__ lo, int n8) {
    int i = blockIdx.x * blockDim.x + threadIdx.x;
    if (i >= n8) return;
    float4 f0 = reinterpret_cast<const float4*>(in)[2*i];
    float4 f1 = reinterpret_cast<const float4*>(in)[2*i + 1];
    reinterpret_cast<uint4*>(hi)[i] = make_uint4(
        pack_h16(f0.x, f0.y), pack_h16(f0.z, f0.w),
        pack_h16(f1.x, f1.y), pack_h16(f1.z, f1.w));
    reinterpret_cast<uint4*>(lo)[i] = make_uint4(
        pack_l16(f0.x, f0.y), pack_l16(f0.z, f0.w),
        pack_l16(f1.x, f1.y), pack_l16(f1.z, f1.w));
}

// ===========================================================================
// Shared warp/thread mapping for 128x128 tile GEMMs
// ===========================================================================
struct GemmCtx {
    uint32_t su;
    int tid, l, w, wm, wn, grp, lr;
    uint32_t a_row[2], b_row[4], a_c16, b_c16;
};

__device__ __forceinline__ void gemm_init(GemmCtx& g, char* smem) {
    g.su = smem_to_u32(smem);
    g.tid = threadIdx.x;
    g.l = g.tid & 31; g.w = g.tid >> 5;
    g.wm = g.w >> 1;  g.wn = g.w & 1;          // 4m x 2n warp grid
    g.grp = g.l >> 3; g.lr = g.l & 7;
    #pragma unroll
    for (int mt = 0; mt < 2; mt++)
        g.a_row[mt] = (uint32_t)((g.wm * 32 + mt * 16 + g.lr + (g.grp & 1) * 8) * 64);
    #pragma unroll
    for (int j = 0; j < 4; j++)
        g.b_row[j] = (uint32_t)((g.wn * 64 + j * 16 + g.lr + (g.grp >> 1) * 8) * 64);
    g.a_c16 = (uint32_t)(g.grp >> 1) * 16;
    g.b_c16 = (uint32_t)(g.grp & 1) * 16;
}

// ===========================================================================
// bf16x3 GEMM body: K-chunk 32, 3-stage (96KB), 2 CTAs/SM.
// stage: Ah 8K | Al 8K | Bh 8K | Bl 8K = 32K
// ===========================================================================
#define GSTAGE 32768
#define GSMEM_BYTES (3 * GSTAGE)

__device__ __forceinline__ void issue_g(uint32_t sb,
    const __nv_bfloat16* a_h, const __nv_bfloat16* a_l,
    const __nv_bfloat16* b_h, const __nv_bfloat16* b_l, int tid)
{
    uint32_t o = (uint32_t)((tid >> 1) * 64 + (tid & 1) * 32);
    uint32_t o0 = o ^ ((o >> 3) & 0x30);
    uint32_t o1 = o0 ^ 16;
    cp16(sb + o0,         a_h);     cp16(sb + o1,         a_h + 8);
    cp16(sb + 8192  + o0, a_l);     cp16(sb + 8192  + o1, a_l + 8);
    cp16(sb + 16384 + o0, b_h);     cp16(sb + 16384 + o1, b_h + 8);
    cp16(sb + 24576 + o0, b_l);     cp16(sb + 24576 + o1, b_l + 8);
}

__device__ __forceinline__ void gemm_body(
    GemmCtx& g,
    const __nv_bfloat16* pa_h, const __nv_bfloat16* pa_l,
    const __nv_bfloat16* pb_h, const __nv_bfloat16* pb_l,
    float acc[2][8][4])
{
    issue_g(g.su,          pa_h,      pa_l,      pb_h,      pb_l,      g.tid); CP_COMMIT();
    issue_g(g.su + GSTAGE, pa_h + 32, pa_l + 32, pb_h + 32, pb_l + 32, g.tid); CP_COMMIT();

    for (int c = 0; c < 64; c++) {
        CP_WAIT(1);
        __syncthreads();
        if (c + 2 < 64) {
            int k0 = (c + 2) * 32;
            issue_g(g.su + (uint32_t)((c + 2) % 3) * GSTAGE,
                    pa_h + k0, pa_l + k0, pb_h + k0, pb_l + k0, g.tid);
        }
        CP_COMMIT();

        const uint32_t cur = g.su + (uint32_t)(c % 3) * GSTAGE;

        #pragma unroll
        for (int ks = 0; ks < 2; ks++) {
            uint32_t ah[2][4], al[2][4];
            #pragma unroll
            for (int mt = 0; mt < 2; mt++) {
                uint32_t off = g.a_row[mt] + (uint32_t)(ks * 32) + g.a_c16;
                off ^= (off >> 3) & 0x30;
                ldx4(ah[mt], cur + off);
                ldx4(al[mt], cur + 8192 + off);
            }
            #pragma unroll
            for (int jp = 0; jp < 2; jp++) {
                uint32_t bh[2][4], bl[2][4];
                #pragma unroll
                for (int u = 0; u < 2; u++) {
                    uint32_t off = g.b_row[2*jp + u] + (uint32_t)(ks * 32) + g.b_c16;
                    off ^= (off >> 3) & 0x30;
                    ldx4(bh[u], cur + 16384 + off);
                    ldx4(bl[u], cur + 24576 + off);
                }
                #pragma unroll
                for (int u = 0; u < 2; u++)
                    #pragma unroll
                    for (int mt = 0; mt < 2; mt++) {
                        mma_bf16(acc[mt][4*jp + 2*u],     ah[mt], bh[u][0], bh[u][1]);
                        mma_bf16(acc[mt][4*jp + 2*u + 1], ah[mt], bh[u][2], bh[u][3]);
                    }
                #pragma unroll
                for (int u = 0; u < 2; u++)
                    #pragma unroll
                    for (int mt = 0; mt < 2; mt++) {
                        mma_bf16(acc[mt][4*jp + 2*u],     ah[mt], bl[u][0], bl[u][1]);
                        mma_bf16(acc[mt][4*jp + 2*u + 1], ah[mt], bl[u][2], bl[u][3]);
                    }
                #pragma unroll
                for (int u = 0; u < 2; u++)
                    #pragma unroll
                    for (int mt = 0; mt < 2; mt++) {
                        mma_bf16(acc[mt][4*jp + 2*u],     al[mt], bh[u][0], bh[u][1]);
                        mma_bf16(acc[mt][4*jp + 2*u + 1], al[mt], bh[u][2], bh[u][3]);
                    }
            }
        }
    }
}

// ---- fused QK projections: grid 1024 = 2 x 512 tiles (wsel-major) ----
__global__ void __launch_bounds__(256, 2) gemm_qk()
{
    extern __shared__ char smem[];
    GemmCtx g; gemm_init(g, smem);

    const int wsel = blockIdx.x >> 9;
    const int tile = blockIdx.x & 511;
    const int m0 = (tile >> 4) * 128, n0 = (tile & 15) * 128;

    const __nv_bfloat16* Bh = wsel ? gwk_h : gwq_h;
    const __nv_bfloat16* Bl = wsel ? gwk_l : gwq_l;
    __nv_bfloat16* Ch = wsel ? gk_h : gq_h;
    __nv_bfloat16* Cl = wsel ? gk_l : gq_l;

    const int sr = g.tid >> 1, sc = (g.tid & 1) * 16;
    const __nv_bfloat16* pa_h = gx_h + (size_t)(m0 + sr) * 2048 + sc;
    const __nv_bfloat16* pa_l = gx_l + (size_t)(m0 + sr) * 2048 + sc;
    const __nv_bfloat16* pb_h = Bh   + (size_t)(n0 + sr) * 2048 + sc;
    const __nv_bfloat16* pb_l = Bl   + (size_t)(n0 + sr) * 2048 + sc;

    float acc[2][8][4];
    #pragma unroll
    for (int mt = 0; mt < 2; mt++)
        #pragma unroll
        for (int nt = 0; nt < 8; nt++)
            #pragma unroll
            for (int i = 0; i < 4; i++) acc[mt][nt][i] = 0.f;

    gemm_body(g, pa_h, pa_l, pb_h, pb_l, acc);

    #pragma unroll
    for (int mt = 0; mt < 2; mt++) {
        #pragma unroll
        for (int nt = 0; nt < 8; nt++) {
            int r  = m0 + g.wm * 32 + mt * 16 + (g.l >> 2);
            int cc = n0 + g.wn * 64 + nt * 8 + 2 * (g.l & 3);
            int b = r >> 11, s = r & 2047, h = cc >> 6, d = cc & 63;
            size_t base = (((size_t)(b * 32 + h)) * 2048 + s) * 64 + d;
            *reinterpret_cast<uint32_t*>(Ch + base) =
                pack_hi(acc[mt][nt][0], acc[mt][nt][1]);
            *reinterpret_cast<uint32_t*>(Cl + base) =
                pack_lo_res(acc[mt][nt][0], acc[mt][nt][1]);
            *reinterpret_cast<uint32_t*>(Ch + base + 8 * 64) =
                pack_hi(acc[mt][nt][2], acc[mt][nt][3]);
            *reinterpret_cast<uint32_t*>(Cl + base + 8 * 64) =
                pack_lo_res(acc[mt][nt][2], acc[mt][nt][3]);
        }
    }
}

// ===========================================================================
// fp16 2-term GEMM body (A single fp16, B fp16 hi/lo).
// stage: Ah 8K | Bh 8K | Bl 8K = 24K, 3 stages = 72KB, 2 CTAs/SM.
// ===========================================================================
#define OSTAGE 24576
#define OSMEM_BYTES (3 * OSTAGE)

__device__ __forceinline__ void issue_o(uint32_t sb,
    const __half* a_h, const __half* b_h, const __half* b_l, int tid)
{
    uint32_t o = (uint32_t)((tid >> 1) * 64 + (tid & 1) * 32);
    uint32_t o0 = o ^ ((o >> 3) & 0x30);
    uint32_t o1 = o0 ^ 16;
    cp16(sb + o0,         a_h);     cp16(sb + o1,         a_h + 8);
    cp16(sb + 8192  + o0, b_h);     cp16(sb + 8192  + o1, b_h + 8);
    cp16(sb + 16384 + o0, b_l);     cp16(sb + 16384 + o1, b_l + 8);
}

__device__ __forceinline__ void gemm2_body(
    GemmCtx& g, const __half* pa_h, const __half* pb_h, const __half* pb_l,
    float acc[2][8][4])
{
    issue_o(g.su,          pa_h,      pb_h,      pb_l,      g.tid); CP_COMMIT();
    issue_o(g.su + OSTAGE, pa_h + 32, pb_h + 32, pb_l + 32, g.tid); CP_COMMIT();

    for (int c = 0; c < 64; c++) {
        CP_WAIT(1);
        __syncthreads();
        if (c + 2 < 64) {
            int k0 = (c + 2) * 32;
            issue_o(g.su + (uint32_t)((c + 2) % 3) * OSTAGE,
                    pa_h + k0, pb_h + k0, pb_l + k0, g.tid);
        }
        CP_COMMIT();

        const uint32_t cur = g.su + (uint32_t)(c % 3) * OSTAGE;

        #pragma unroll
        for (int ks = 0; ks < 2; ks++) {
            uint32_t ah[2][4];
            #pragma unroll
            for (int mt = 0; mt < 2; mt++) {
                uint32_t off = g.a_row[mt] + (uint32_t)(ks * 32) + g.a_c16;
                off ^= (off >> 3) & 0x30;
                ldx4(ah[mt], cur + off);
            }
            #pragma unroll
            for (int jp = 0; jp < 2; jp++) {
                uint32_t bh[2][4], bl[2][4];
                #pragma unroll
                for (int u = 0; u < 2; u++) {
                    uint32_t off = g.b_row[2*jp + u] + (uint32_t)(ks * 32) + g.b_c16;
                    off ^= (off >> 3) & 0x30;
                    ldx4(bh[u], cur + 8192  + off);
                    ldx4(bl[u], cur + 16384 + off);
                }
                #pragma unroll
                for (int u = 0; u < 2; u++)
                    #pragma unroll
                    for (int mt = 0; mt < 2; mt++) {
                        mma_f16(acc[mt][4*jp + 2*u],     ah[mt], bh[u][0], bh[u][1]);
                        mma_f16(acc[mt][4*jp + 2*u + 1], ah[mt], bh[u][2], bh[u][3]);
                    }
                #pragma unroll
                for (int u = 0; u < 2; u++)
                    #pragma unroll
                    for (int mt = 0; mt < 2; mt++) {
                        mma_f16(acc[mt][4*jp + 2*u],     ah[mt], bl[u][0], bl[u][1]);
                        mma_f16(acc[mt][4*jp + 2*u + 1], ah[mt], bl[u][2], bl[u][3]);
                    }
            }
        }
    }
}

// ---- V projection: fp16 2-term, PERM fp16 output -> gv16 ----
__global__ void __launch_bounds__(256, 2) gemm_v()
{
    extern __shared__ char smem[];
    GemmCtx g; gemm_init(g, smem);
    const int m0 = (blockIdx.x >> 4) * 128, n0 = (blockIdx.x & 15) * 128;

    const int sr = g.tid >> 1, sc = (g.tid & 1) * 16;
    const __half* pa_h = gx16  + (size_t)(m0 + sr) * 2048 + sc;
    const __half* pb_h = gwv_h + (size_t)(n0 + sr) * 2048 + sc;
    const __half* pb_l = gwv_l + (size_t)(n0 + sr) * 2048 + sc;

    float acc[2][8][4];
    #pragma unroll
    for (int mt = 0; mt < 2; mt++)
        #pragma unroll
        for (int nt = 0; nt < 8; nt++)
            #pragma unroll
            for (int i = 0; i < 4; i++) acc[mt][nt][i] = 0.f;

    gemm2_body(g, pa_h, pb_h, pb_l, acc);

    #pragma unroll
    for (int mt = 0; mt < 2; mt++) {
        #pragma unroll
        for (int nt = 0; nt < 8; nt++) {
            int r  = m0 + g.wm * 32 + mt * 16 + (g.l >> 2);
            int cc = n0 + g.wn * 64 + nt * 8 + 2 * (g.l & 3);
            int b = r >> 11, s = r & 2047, h = cc >> 6, d = cc & 63;
            size_t base = (((size_t)(b * 32 + h)) * 2048 + s) * 64 + d;
            *reinterpret_cast<uint32_t*>(gv16 + base) =
                pack_h16(acc[mt][nt][0], acc[mt][nt][1]);
            *reinterpret_cast<uint32_t*>(gv16 + base + 8 * 64) =
                pack_h16(acc[mt][nt][2], acc[mt][nt][3]);
        }
    }
}

// ---- output projection: fp16 2-term, fp32 C ----
__global__ void __launch_bounds__(256, 2) gemm_out(float* __restrict__ Cf)
{
    extern __shared__ char smem[];
    GemmCtx g; gemm_init(g, smem);
    const int m0 = (blockIdx.x >> 4) * 128, n0 = (blockIdx.x & 15) * 128;

    const int sr = g.tid >> 1, sc = (g.tid & 1) * 16;
    const __half* pa_h = gc_h  + (size_t)(m0 + sr) * 2048 + sc;
    const __half* pb_h = gwo_h + (size_t)(n0 + sr) * 2048 + sc;
    const __half* pb_l = gwo_l + (size_t)(n0 + sr) * 2048 + sc;

    float acc[2][8][4];
    #pragma unroll
    for (int mt = 0; mt < 2; mt++)
        #pragma unroll
        for (int nt = 0; nt < 8; nt++)
            #pragma unroll
            for (int i = 0; i < 4; i++) acc[mt][nt][i] = 0.f;

    gemm2_body(g, pa_h, pb_h, pb_l, acc);

    #pragma unroll
    for (int mt = 0; mt < 2; mt++) {
        #pragma unroll
        for (int nt = 0; nt < 8; nt++) {
            int r  = m0 + g.wm * 32 + mt * 16 + (g.l >> 2);
            int cc = n0 + g.wn * 64 + nt * 8 + 2 * (g.l & 3);
            *reinterpret_cast<float2*>(Cf + (size_t)r * 2048 + cc) =
                make_float2(acc[mt][nt][0], acc[mt][nt][1]);
            *reinterpret_cast<float2*>(Cf + (size_t)(r + 8) * 2048 + cc) =
                make_float2(acc[mt][nt][2], acc[mt][nt][3]);
        }
    }
}

// ===========================================================================
// relative-position bucket (exact integer T5 formula) + bias table
// ===========================================================================
__device__ __forceinline__ int rel_bucket(int dist) {
    int rel = dist > 0 ? 16 : 0;
    int d = abs(dist);
    int sb;
    if (d < 8)       sb = d;
    else if (d < 12) sb = 8;
    else if (d < 16) sb = 9;
    else if (d < 23) sb = 10;
    else if (d < 32) sb = 11;
    else if (d < 46) sb = 12;
    else if (d < 64) sb = 13;
    else if (d < 91) sb = 14;
    else             sb = 15;
    return rel + sb;
}

__global__ void bias_table_kernel(const float* __restrict__ rel_bias) {
    int idx = blockIdx.x * blockDim.x + threadIdx.x;
    if (idx >= HH * 4095) return;
    int h = idx / 4095;
    int di = idx % 4095;
    g_biastab[h * 4096 + di] = rel_bias[rel_bucket(di - 2047) * HH + h];
}

// ===========================================================================
// FA2-style attention: QK bf16x3 (score path), PV 1-term fp16 (value path).
// KV tile 128 (16 iters) + folded bias write. ctx stored fp16-hi only.
// smem: Qh 16K | Ql 16K | 2 x { Kh 16K Kl 16K Vh 16K } | 2 x bias 1K = 130K
// ===========================================================================
#define AKV 49152
#define ABIAS (32768 + 2*AKV)
#define ASMEM_BYTES (ABIAS + 2*1024)

__global__ void __launch_bounds__(256, 1) attn_mma(float* __restrict__ out_bias)
{
    extern __shared__ char smem[];
    const uint32_t su = smem_to_u32(smem);
    const int tid = threadIdx.x, l = tid & 31, w = tid >> 5;
    const int grp = l >> 3, lr = l & 7;
    const int bh = blockIdx.y, h = bh & 31, b = bh >> 5;
    const int q0 = blockIdx.x * 128;
    const size_t bhoff = (size_t)bh * SS * HD;
    const int r2 = tid >> 1, hf = tid & 1;

    // Q tiles -> smem (part of group 0)
    {
        const __nv_bfloat16* sh = gq_h + bhoff + (size_t)(q0 + r2) * 64 + hf * 32;
        const __nv_bfloat16* sl = gq_l + bhoff + (size_t)(q0 + r2) * 64 + hf * 32;
        uint32_t dd = (uint32_t)(r2 * 128 + hf * 64);
        #pragma unroll
        for (int i = 0; i < 4; i++) {
            uint32_t o = dd + i * 16; o ^= (o >> 3) & 0x70;
            cp16(su + o,         sh + i * 8);
            cp16(su + 16384 + o, sl + i * 8);
        }
    }

    // KV + bias issue for ktile kt: Kh, Kl (bf16), Vh (fp16)
    auto issue_kv = [&](int kt) {
        uint32_t sb = su + 32768 + (uint32_t)(kt & 1) * AKV;
        size_t off = bhoff + (size_t)(kt * 128 + r2) * 64 + hf * 32;
        const uint32_t dd = (uint32_t)(r2 * 128 + hf * 64);
        #pragma unroll
        for (int i = 0; i < 4; i++) {
            uint32_t o = dd + i * 16; o ^= (o >> 3) & 0x70;
            cp16(sb + o,         gk_h + off + i * 8);
            cp16(sb + 16384 + o, gk_l + off + i * 8);
            cp16(sb + 32768 + o, gv16 + off + i * 8);
        }
        int w0 = kt * 128 - q0 + 1920;
        cp4(su + ABIAS + (uint32_t)(kt & 1) * 1024 + tid * 4,
            &g_biastab[h * 4096 + w0 + tid]);
    };
    issue_kv(0); CP_COMMIT();
    issue_kv(1); CP_COMMIT();

    float o[8][4];
    #pragma unroll
    for (int nt = 0; nt < 8; nt++)
        #pragma unroll
        for (int i = 0; i < 4; i++) o[nt][i] = 0.f;
    float mrow[2] = {-1e30f, -1e30f};
    float lrow[2] = {0.f, 0.f};

    const uint32_t qbase  = (uint32_t)((w * 16 + lr + (grp & 1) * 8) * 128 + (grp >> 1) * 16);
    const uint32_t kvbase = (uint32_t)((lr + (grp >> 1) * 8) * 128 + (grp & 1) * 16);

    for (int kt = 0; kt < 16; kt++) {
        CP_WAIT(1);
        __syncthreads();
        const uint32_t SB = su + 32768 + (uint32_t)(kt & 1) * AKV;
        const float* bsm = reinterpret_cast<const float*>(
            smem + ABIAS + (kt & 1) * 1024);

        // ---- S = Q K^T (bf16x3, term-major) ----
        float s[16][4];
        #pragma unroll
        for (int j = 0; j < 16; j++)
            #pragma unroll
            for (int i = 0; i < 4; i++) s[j][i] = 0.f;

        #pragma unroll
        for (int ks = 0; ks < 4; ks++) {
            uint32_t qo = qbase + (uint32_t)(ks * 32); qo ^= (qo >> 3) & 0x70;
            uint32_t ah[4], al[4];
            ldx4(ah, su + qo);
            ldx4(al, su + 16384 + qo);
            #pragma unroll
            for (int jp = 0; jp < 4; jp++) {
                uint32_t kh[2][4], kl[2][4];
                #pragma unroll
                for (int u = 0; u < 2; u++) {
                    uint32_t ko = kvbase + (uint32_t)((2*jp + u) * 2048 + ks * 32);
                    ko ^= (ko >> 3) & 0x70;
                    ldx4(kh[u], SB + ko);
                    ldx4(kl[u], SB + 16384 + ko);
                }
                #pragma unroll
                for (int u = 0; u < 2; u++) {
                    mma_bf16(s[4*jp + 2*u],     ah, kh[u][0], kh[u][1]);
                    mma_bf16(s[4*jp + 2*u + 1], ah, kh[u][2], kh[u][3]);
                }
                #pragma unroll
                for (int u = 0; u < 2; u++) {
                    mma_bf16(s[4*jp + 2*u],     ah, kl[u][0], kl[u][1]);
                    mma_bf16(s[4*jp + 2*u + 1], ah, kl[u][2], kl[u][3]);
                }
                #pragma unroll
                for (int u = 0; u < 2; u++) {
                    mma_bf16(s[4*jp + 2*u],     al, kh[u][0], kh[u][1]);
                    mma_bf16(s[4*jp + 2*u + 1], al, kh[u][2], kh[u][3]);
                }
            }
        }

        // ---- bias + online softmax ----
        const int bb = 127 - (w * 16 + (l >> 2)) + 2 * (l & 3);
        #pragma unroll
        for (int j = 0; j < 16; j++) {
            s[j][0] += bsm[bb + 8*j];
            s[j][1] += bsm[bb + 8*j + 1];
            s[j][2] += bsm[bb + 8*j - 8];
            s[j][3] += bsm[bb + 8*j - 7];
        }
        #pragma unroll
        for (int u = 0; u < 2; u++) {
            float mx = -1e30f;
            #pragma unroll
            for (int j = 0; j < 16; j++)
                mx = fmaxf(mx, fmaxf(s[j][2*u], s[j][2*u+1]));
            mx = fmaxf(mx, __shfl_xor_sync(0xffffffffu, mx, 1));
            mx = fmaxf(mx, __shfl_xor_sync(0xffffffffu, mx, 2));
            float mnew = fmaxf(mrow[u], mx);
            float scale = __expf(mrow[u] - mnew);
            mrow[u] = mnew;
            float sum = 0.f;
            #pragma unroll
            for (int j = 0; j < 16; j++) {
                float p0 = __expf(s[j][2*u]   - mnew);
                float p1 = __expf(s[j][2*u+1] - mnew);
                s[j][2*u] = p0; s[j][2*u+1] = p1;
                sum += p0 + p1;
            }
            sum += __shfl_xor_sync(0xffffffffu, sum, 1);
            sum += __shfl_xor_sync(0xffffffffu, sum, 2);
            lrow[u] = lrow[u] * scale + sum;
            #pragma unroll
            for (int nt = 0; nt < 8; nt++) {
                o[nt][2*u]   *= scale;
                o[nt][2*u+1] *= scale;
            }
        }

        // ---- O += P V (1-term fp16: P fp16-hi, V fp16-hi) ----
        #pragma unroll
        for (int ks = 0; ks < 8; ks++) {
            uint32_t aph[4];
            aph[0] = pack_h16(s[2*ks][0],   s[2*ks][1]);
            aph[1] = pack_h16(s[2*ks][2],   s[2*ks][3]);
            aph[2] = pack_h16(s[2*ks+1][0], s[2*ks+1][1]);
            aph[3] = pack_h16(s[2*ks+1][2], s[2*ks+1][3]);
            #pragma unroll
            for (int dp = 0; dp < 2; dp++) {
                uint32_t vh[2][4];
                #pragma unroll
                for (int u = 0; u < 2; u++) {
                    uint32_t vo = kvbase + (uint32_t)(ks * 2048 + (2*dp + u) * 32);
                    vo ^= (vo >> 3) & 0x70;
                    ldx4t(vh[u], SB + 32768 + vo);
                }
                #pragma unroll
                for (int u = 0; u < 2; u++) {
                    mma_f16(o[4*dp + 2*u],     aph, vh[u][0], vh[u][2]);
                    mma_f16(o[4*dp + 2*u + 1], aph, vh[u][1], vh[u][3]);
                }
            }
        }

        // ---- folded position_bias materialization (b==0 CTAs only) ----
        if (b == 0) {
            const int q = tid >> 1;          // 0..127
            const int kh2 = (tid & 1) * 64;  // 0 or 64
            float* dst = out_bias + ((size_t)h * 2048 + (q0 + q)) * 2048
                                  + kt * 128 + kh2;
            const int bidx = kh2 - q + 127;
            #pragma unroll
            for (int i = 0; i < 16; i++) {
                *reinterpret_cast<float4*>(dst + 4*i) =
                    make_float4(bsm[bidx + 4*i],     bsm[bidx + 4*i + 1],
                                bsm[bidx + 4*i + 2], bsm[bidx + 4*i + 3]);
            }
        }

        __syncthreads();
        if (kt + 2 < 16) issue_kv(kt + 2);
        CP_COMMIT();
    }

    // ---- epilogue: normalize, fp16-hi store of ctx ----
    const float inv0 = 1.f / lrow[0], inv1 = 1.f / lrow[1];
    const int rg0 = b * 2048 + q0 + w * 16 + (l >> 2);
    const size_t base0 = (size_t)rg0 * 2048 + h * 64 + 2 * (l & 3);
    const size_t base1 = base0 + (size_t)8 * 2048;
    #pragma unroll
    for (int nt = 0; nt < 8; nt++) {
        float a0 = o[nt][0] * inv0, a1 = o[nt][1] * inv0;
        float a2 = o[nt][2] * inv1, a3 = o[nt][3] * inv1;
        *reinterpret_cast<uint32_t*>(gc_h + base0 + nt * 8) = pack_h16(a0, a1);
        *reinterpret_cast<uint32_t*>(gc_h + base1 + nt * 8) = pack_h16(a2, a3);
    }
}

// ===========================================================================

extern "C" void kernel_launch(void* const* d_in, const int* in_sizes, int n_in,
                              void* d_out, int out_size)
{
    (void)in_sizes; (void)n_in; (void)out_size;
    const float* x  = (const float*)d_in[0];
    const float* wq = (const float*)d_in[1];
    const float* wk = (const float*)d_in[2];
    const float* wv = (const float*)d_in[3];
    const float* wo = (const float*)d_in[4];
    const float* rb = (const float*)d_in[5];
    float* out      = (float*)d_out;
    float* out_bias = out + (size_t)BB * SS * MD;

    __nv_bfloat16 *wqh,*wql,*wkh,*wkl;
    __half *wvh,*wvl,*woh,*wol;
    cudaGetSymbolAddress((void**)&wqh, gwq_h); cudaGetSymbolAddress((void**)&wql, gwq_l);
    cudaGetSymbolAddress((void**)&wkh, gwk_h); cudaGetSymbolAddress((void**)&wkl, gwk_l);
    cudaGetSymbolAddress((void**)&wvh, gwv_h); cudaGetSymbolAddress((void**)&wvl, gwv_l);
    cudaGetSymbolAddress((void**)&woh, gwo_h); cudaGetSymbolAddress((void**)&wol, gwo_l);

    cudaFuncSetAttribute(gemm_qk,  cudaFuncAttributeMaxDynamicSharedMemorySize, GSMEM_BYTES);
    cudaFuncSetAttribute(gemm_v,   cudaFuncAttributeMaxDynamicSharedMemorySize, OSMEM_BYTES);
    cudaFuncSetAttribute(gemm_out, cudaFuncAttributeMaxDynamicSharedMemorySize, OSMEM_BYTES);
    cudaFuncSetAttribute(attn_mma, cudaFuncAttributeMaxDynamicSharedMemorySize, ASMEM_BYTES);

    // one-shot conversions + bias table
    convert_x_kernel<<<(MTOT*MD/8 + 255)/256, 256>>>(x, MTOT*MD/8);
    convert_kernel<<<(MD*MD/8 + 255)/256, 256>>>(wq, wqh, wql, MD*MD/8);
    convert_kernel<<<(MD*MD/8 + 255)/256, 256>>>(wk, wkh, wkl, MD*MD/8);
    convert_f16_kernel<<<(MD*MD/8 + 255)/256, 256>>>(wv, wvh, wvl, MD*MD/8);
    convert_f16_kernel<<<(MD*MD/8 + 255)/256, 256>>>(wo, woh, wol, MD*MD/8);
    bias_table_kernel<<<(HH*4095 + 255)/256, 256>>>(rb);

    // projections
    gemm_qk<<<1024, 256, GSMEM_BYTES>>>();
    gemm_v<<<512, 256, OSMEM_BYTES>>>();

    // attention (QK bf16x3, PV fp16 1-term) + position_bias materialization
    attn_mma<<<dim3(16, 64), 256, ASMEM_BYTES>>>(out_bias);

    // output projection (fp16 2-term, fp32 out)
    gemm_out<<<512, 256, OSMEM_BYTES>>>(out);
}

// round 15
// speedup vs baseline: 1.4144x; 1.1589x over previous
#include <cuda_runtime.h>
#include <cuda_bf16.h>
#include <cuda_fp16.h>
#include <cstdint>
#include <math.h>

#define BB 2
#define SS 2048
#define HH 32
#define HD 64
#define MD 2048
#define MTOT (BB*SS)

// ---------------- device scratch (static, no allocation) ----------------
__device__ __nv_bfloat16 gx_h[MTOT*MD],  gx_l[MTOT*MD];
__device__ __half        gx16[MTOT*MD];                    // x fp16 (V path)
__device__ __nv_bfloat16 gwq_h[MD*MD],   gwq_l[MD*MD];
__device__ __nv_bfloat16 gwk_h[MD*MD],   gwk_l[MD*MD];
__device__ __half        gwv16[MD*MD];                     // wv fp16-hi (1-term)
__device__ __half        gwo16[MD*MD];                     // wo fp16-hi (1-term)
__device__ __nv_bfloat16 gq_h[MTOT*MD],  gq_l[MTOT*MD];    // [bh][s][64]
__device__ __nv_bfloat16 gk_h[MTOT*MD],  gk_l[MTOT*MD];
__device__ __half        gv16[MTOT*MD];                    // v fp16-hi only
__device__ __half        gc_h[MTOT*MD];                    // ctx fp16-hi only
__device__ float g_biastab[HH*4096];

// ---------------- small helpers ----------------
__device__ __forceinline__ uint32_t smem_to_u32(const void* p) {
    uint32_t a;
    asm("{ .reg .u64 t; cvta.to.shared.u64 t, %1; cvt.u32.u64 %0, t; }" : "=r"(a) : "l"(p));
    return a;
}
__device__ __forceinline__ void cp16(uint32_t dst, const void* src) {
    asm volatile("cp.async.cg.shared.global [%0], [%1], 16;" :: "r"(dst), "l"(src));
}
__device__ __forceinline__ void cp4(uint32_t dst, const void* src) {
    asm volatile("cp.async.ca.shared.global [%0], [%1], 4;" :: "r"(dst), "l"(src));
}
#define CP_COMMIT() asm volatile("cp.async.commit_group;" ::: "memory")
#define CP_WAIT(n)  asm volatile("cp.async.wait_group %0;" :: "n"(n) : "memory")

__device__ __forceinline__ void ldx4(uint32_t* r, uint32_t addr) {
    asm volatile("ldmatrix.sync.aligned.m8n8.x4.shared.b16 {%0,%1,%2,%3}, [%4];"
                 : "=r"(r[0]), "=r"(r[1]), "=r"(r[2]), "=r"(r[3]) : "r"(addr));
}
__device__ __forceinline__ void ldx4t(uint32_t* r, uint32_t addr) {
    asm volatile("ldmatrix.sync.aligned.m8n8.x4.trans.shared.b16 {%0,%1,%2,%3}, [%4];"
                 : "=r"(r[0]), "=r"(r[1]), "=r"(r[2]), "=r"(r[3]) : "r"(addr));
}
__device__ __forceinline__ void mma_bf16(float* d, const uint32_t* a,
                                         uint32_t b0, uint32_t b1) {
    asm volatile(
        "mma.sync.aligned.m16n8k16.row.col.f32.bf16.bf16.f32 "
        "{%0,%1,%2,%3}, {%4,%5,%6,%7}, {%8,%9}, {%0,%1,%2,%3};"
        : "+f"(d[0]), "+f"(d[1]), "+f"(d[2]), "+f"(d[3])
        : "r"(a[0]), "r"(a[1]), "r"(a[2]), "r"(a[3]), "r"(b0), "r"(b1));
}
__device__ __forceinline__ void mma_f16(float* d, const uint32_t* a,
                                        uint32_t b0, uint32_t b1) {
    asm volatile(
        "mma.sync.aligned.m16n8k16.row.col.f32.f16.f16.f32 "
        "{%0,%1,%2,%3}, {%4,%5,%6,%7}, {%8,%9}, {%0,%1,%2,%3};"
        : "+f"(d[0]), "+f"(d[1]), "+f"(d[2]), "+f"(d[3])
        : "r"(a[0]), "r"(a[1]), "r"(a[2]), "r"(a[3]), "r"(b0), "r"(b1));
}

__device__ __forceinline__ uint32_t pack_hi(float a, float b) {
    return __byte_perm(__float_as_uint(a), __float_as_uint(b), 0x7632);
}
__device__ __forceinline__ uint32_t pack_lo_res(float a, float b) {
    float ra = a - __uint_as_float(__float_as_uint(a) & 0xffff0000u);
    float rb = b - __uint_as_float(__float_as_uint(b) & 0xffff0000u);
    uint32_t r;
    asm("cvt.rn.bf16x2.f32 %0, %1, %2;" : "=r"(r) : "f"(rb), "f"(ra));
    return r;
}
__device__ __forceinline__ uint32_t pack_h16(float a, float b) {
    uint32_t r;
    asm("cvt.rn.f16x2.f32 %0, %1, %2;" : "=r"(r) : "f"(b), "f"(a));
    return r;
}

// x -> bf16 hi/lo + fp16 single, one pass
__global__ void convert_x_kernel(const float* __restrict__ in, int n8) {
    int i = blockIdx.x * blockDim.x + threadIdx.x;
    if (i >= n8) return;
    float4 f0 = reinterpret_cast<const float4*>(in)[2*i];
    float4 f1 = reinterpret_cast<const float4*>(in)[2*i + 1];
    reinterpret_cast<uint4*>(gx_h)[i] = make_uint4(
        pack_hi(f0.x, f0.y), pack_hi(f0.z, f0.w),
        pack_hi(f1.x, f1.y), pack_hi(f1.z, f1.w));
    reinterpret_cast<uint4*>(gx_l)[i] = make_uint4(
        pack_lo_res(f0.x, f0.y), pack_lo_res(f0.z, f0.w),
        pack_lo_res(f1.x, f1.y), pack_lo_res(f1.z, f1.w));
    reinterpret_cast<uint4*>(gx16)[i] = make_uint4(
        pack_h16(f0.x, f0.y), pack_h16(f0.z, f0.w),
        pack_h16(f1.x, f1.y), pack_h16(f1.z, f1.w));
}
// fp32 -> bf16 hi/lo
__global__ void convert_kernel(const float* __restrict__ in,
                               __nv_bfloat16* __restrict__ hi,
                               __nv_bfloat16* __restrict__ lo, int n8) {
    int i = blockIdx.x * blockDim.x + threadIdx.x;
    if (i >= n8) return;
    float4 f0 = reinterpret_cast<const float4*>(in)[2*i];
    float4 f1 = reinterpret_cast<const float4*>(in)[2*i + 1];
    reinterpret_cast<uint4*>(hi)[i] = make_uint4(
        pack_hi(f0.x, f0.y), pack_hi(f0.z, f0.w),
        pack_hi(f1.x, f1.y), pack_hi(f1.z, f1.w));
    reinterpret_cast<uint4*>(lo)[i] = make_uint4(
        pack_lo_res(f0.x, f0.y), pack_lo_res(f0.z, f0.w),
        pack_lo_res(f1.x, f1.y), pack_lo_res(f1.z, f1.w));
}
// fp32 -> fp16 hi only
__global__ void convert_f16h_kernel(const float* __restrict__ in,
                                    __half* __restrict__ hi, int n8) {
    int i = blockIdx.x * blockDim.x + threadIdx.x;
    if (i >= n8) return;
    float4 f0 = reinterpret_cast<const float4*>(in)[2*i];
    float4 f1 = reinterpret_cast<const float4*>(in)[2*i + 1];
    reinterpret_cast<uint4*>(hi)[i] = make_uint4(
        pack_h16(f0.x, f0.y), pack_h16(f0.z, f0.w),
        pack_h16(f1.x, f1.y), pack_h16(f1.z, f1.w));
}

// ===========================================================================
// Shared warp/thread mapping for 128x128 tile GEMMs
// ===========================================================================
struct GemmCtx {
    uint32_t su;
    int tid, l, w, wm, wn, grp, lr;
    uint32_t a_row[2], b_row[4], a_c16, b_c16;
};

__device__ __forceinline__ void gemm_init(GemmCtx& g, char* smem) {
    g.su = smem_to_u32(smem);
    g.tid = threadIdx.x;
    g.l = g.tid & 31; g.w = g.tid >> 5;
    g.wm = g.w >> 1;  g.wn = g.w & 1;          // 4m x 2n warp grid
    g.grp = g.l >> 3; g.lr = g.l & 7;
    #pragma unroll
    for (int mt = 0; mt < 2; mt++)
        g.a_row[mt] = (uint32_t)((g.wm * 32 + mt * 16 + g.lr + (g.grp & 1) * 8) * 64);
    #pragma unroll
    for (int j = 0; j < 4; j++)
        g.b_row[j] = (uint32_t)((g.wn * 64 + j * 16 + g.lr + (g.grp >> 1) * 8) * 64);
    g.a_c16 = (uint32_t)(g.grp >> 1) * 16;
    g.b_c16 = (uint32_t)(g.grp & 1) * 16;
}

// ===========================================================================
// bf16x3 GEMM body: K-chunk 32, 3-stage (96KB), 2 CTAs/SM.
// stage: Ah 8K | Al 8K | Bh 8K | Bl 8K = 32K
// ===========================================================================
#define GSTAGE 32768
#define GSMEM_BYTES (3 * GSTAGE)

__device__ __forceinline__ void issue_g(uint32_t sb,
    const __nv_bfloat16* a_h, const __nv_bfloat16* a_l,
    const __nv_bfloat16* b_h, const __nv_bfloat16* b_l, int tid)
{
    uint32_t o = (uint32_t)((tid >> 1) * 64 + (tid & 1) * 32);
    uint32_t o0 = o ^ ((o >> 3) & 0x30);
    uint32_t o1 = o0 ^ 16;
    cp16(sb + o0,         a_h);     cp16(sb + o1,         a_h + 8);
    cp16(sb + 8192  + o0, a_l);     cp16(sb + 8192  + o1, a_l + 8);
    cp16(sb + 16384 + o0, b_h);     cp16(sb + 16384 + o1, b_h + 8);
    cp16(sb + 24576 + o0, b_l);     cp16(sb + 24576 + o1, b_l + 8);
}

__device__ __forceinline__ void gemm_body(
    GemmCtx& g,
    const __nv_bfloat16* pa_h, const __nv_bfloat16* pa_l,
    const __nv_bfloat16* pb_h, const __nv_bfloat16* pb_l,
    float acc[2][8][4])
{
    issue_g(g.su,          pa_h,      pa_l,      pb_h,      pb_l,      g.tid); CP_COMMIT();
    issue_g(g.su + GSTAGE, pa_h + 32, pa_l + 32, pb_h + 32, pb_l + 32, g.tid); CP_COMMIT();

    for (int c = 0; c < 64; c++) {
        CP_WAIT(1);
        __syncthreads();
        if (c + 2 < 64) {
            int k0 = (c + 2) * 32;
            issue_g(g.su + (uint32_t)((c + 2) % 3) * GSTAGE,
                    pa_h + k0, pa_l + k0, pb_h + k0, pb_l + k0, g.tid);
        }
        CP_COMMIT();

        const uint32_t cur = g.su + (uint32_t)(c % 3) * GSTAGE;

        #pragma unroll
        for (int ks = 0; ks < 2; ks++) {
            uint32_t ah[2][4], al[2][4];
            #pragma unroll
            for (int mt = 0; mt < 2; mt++) {
                uint32_t off = g.a_row[mt] + (uint32_t)(ks * 32) + g.a_c16;
                off ^= (off >> 3) & 0x30;
                ldx4(ah[mt], cur + off);
                ldx4(al[mt], cur + 8192 + off);
            }
            #pragma unroll
            for (int jp = 0; jp < 2; jp++) {
                uint32_t bh[2][4], bl[2][4];
                #pragma unroll
                for (int u = 0; u < 2; u++) {
                    uint32_t off = g.b_row[2*jp + u] + (uint32_t)(ks * 32) + g.b_c16;
                    off ^= (off >> 3) & 0x30;
                    ldx4(bh[u], cur + 16384 + off);
                    ldx4(bl[u], cur + 24576 + off);
                }
                #pragma unroll
                for (int u = 0; u < 2; u++)
                    #pragma unroll
                    for (int mt = 0; mt < 2; mt++) {
                        mma_bf16(acc[mt][4*jp + 2*u],     ah[mt], bh[u][0], bh[u][1]);
                        mma_bf16(acc[mt][4*jp + 2*u + 1], ah[mt], bh[u][2], bh[u][3]);
                    }
                #pragma unroll
                for (int u = 0; u < 2; u++)
                    #pragma unroll
                    for (int mt = 0; mt < 2; mt++) {
                        mma_bf16(acc[mt][4*jp + 2*u],     ah[mt], bl[u][0], bl[u][1]);
                        mma_bf16(acc[mt][4*jp + 2*u + 1], ah[mt], bl[u][2], bl[u][3]);
                    }
                #pragma unroll
                for (int u = 0; u < 2; u++)
                    #pragma unroll
                    for (int mt = 0; mt < 2; mt++) {
                        mma_bf16(acc[mt][4*jp + 2*u],     al[mt], bh[u][0], bh[u][1]);
                        mma_bf16(acc[mt][4*jp + 2*u + 1], al[mt], bh[u][2], bh[u][3]);
                    }
            }
        }
    }
}

// ---- fused QK projections: grid 1024 = 2 x 512 tiles (wsel-major) ----
__global__ void __launch_bounds__(256, 2) gemm_qk()
{
    extern __shared__ char smem[];
    GemmCtx g; gemm_init(g, smem);

    const int wsel = blockIdx.x >> 9;
    const int tile = blockIdx.x & 511;
    const int m0 = (tile >> 4) * 128, n0 = (tile & 15) * 128;

    const __nv_bfloat16* Bh = wsel ? gwk_h : gwq_h;
    const __nv_bfloat16* Bl = wsel ? gwk_l : gwq_l;
    __nv_bfloat16* Ch = wsel ? gk_h : gq_h;
    __nv_bfloat16* Cl = wsel ? gk_l : gq_l;

    const int sr = g.tid >> 1, sc = (g.tid & 1) * 16;
    const __nv_bfloat16* pa_h = gx_h + (size_t)(m0 + sr) * 2048 + sc;
    const __nv_bfloat16* pa_l = gx_l + (size_t)(m0 + sr) * 2048 + sc;
    const __nv_bfloat16* pb_h = Bh   + (size_t)(n0 + sr) * 2048 + sc;
    const __nv_bfloat16* pb_l = Bl   + (size_t)(n0 + sr) * 2048 + sc;

    float acc[2][8][4];
    #pragma unroll
    for (int mt = 0; mt < 2; mt++)
        #pragma unroll
        for (int nt = 0; nt < 8; nt++)
            #pragma unroll
            for (int i = 0; i < 4; i++) acc[mt][nt][i] = 0.f;

    gemm_body(g, pa_h, pa_l, pb_h, pb_l, acc);

    #pragma unroll
    for (int mt = 0; mt < 2; mt++) {
        #pragma unroll
        for (int nt = 0; nt < 8; nt++) {
            int r  = m0 + g.wm * 32 + mt * 16 + (g.l >> 2);
            int cc = n0 + g.wn * 64 + nt * 8 + 2 * (g.l & 3);
            int b = r >> 11, s = r & 2047, h = cc >> 6, d = cc & 63;
            size_t base = (((size_t)(b * 32 + h)) * 2048 + s) * 64 + d;
            *reinterpret_cast<uint32_t*>(Ch + base) =
                pack_hi(acc[mt][nt][0], acc[mt][nt][1]);
            *reinterpret_cast<uint32_t*>(Cl + base) =
                pack_lo_res(acc[mt][nt][0], acc[mt][nt][1]);
            *reinterpret_cast<uint32_t*>(Ch + base + 8 * 64) =
                pack_hi(acc[mt][nt][2], acc[mt][nt][3]);
            *reinterpret_cast<uint32_t*>(Cl + base + 8 * 64) =
                pack_lo_res(acc[mt][nt][2], acc[mt][nt][3]);
        }
    }
}

// ===========================================================================
// fp16 1-term GEMM body (A fp16, B fp16).
// stage: Ah 8K | Bh 8K = 16K, 3 stages = 48K, 2 CTAs/SM.
// ===========================================================================
#define O1STAGE 16384
#define O1SMEM_BYTES (3 * O1STAGE)

__device__ __forceinline__ void issue_1(uint32_t sb,
    const __half* a_h, const __half* b_h, int tid)
{
    uint32_t o = (uint32_t)((tid >> 1) * 64 + (tid & 1) * 32);
    uint32_t o0 = o ^ ((o >> 3) & 0x30);
    uint32_t o1 = o0 ^ 16;
    cp16(sb + o0,        a_h);     cp16(sb + o1,        a_h + 8);
    cp16(sb + 8192 + o0, b_h);     cp16(sb + 8192 + o1, b_h + 8);
}

__device__ __forceinline__ void gemm1_body(
    GemmCtx& g, const __half* pa_h, const __half* pb_h, float acc[2][8][4])
{
    issue_1(g.su,           pa_h,      pb_h,      g.tid); CP_COMMIT();
    issue_1(g.su + O1STAGE, pa_h + 32, pb_h + 32, g.tid); CP_COMMIT();

    for (int c = 0; c < 64; c++) {
        CP_WAIT(1);
        __syncthreads();
        if (c + 2 < 64) {
            int k0 = (c + 2) * 32;
            issue_1(g.su + (uint32_t)((c + 2) % 3) * O1STAGE,
                    pa_h + k0, pb_h + k0, g.tid);
        }
        CP_COMMIT();

        const uint32_t cur = g.su + (uint32_t)(c % 3) * O1STAGE;

        #pragma unroll
        for (int ks = 0; ks < 2; ks++) {
            uint32_t ah[2][4];
            #pragma unroll
            for (int mt = 0; mt < 2; mt++) {
                uint32_t off = g.a_row[mt] + (uint32_t)(ks * 32) + g.a_c16;
                off ^= (off >> 3) & 0x30;
                ldx4(ah[mt], cur + off);
            }
            #pragma unroll
            for (int jp = 0; jp < 2; jp++) {
                uint32_t bh[2][4];
                #pragma unroll
                for (int u = 0; u < 2; u++) {
                    uint32_t off = g.b_row[2*jp + u] + (uint32_t)(ks * 32) + g.b_c16;
                    off ^= (off >> 3) & 0x30;
                    ldx4(bh[u], cur + 8192 + off);
                }
                #pragma unroll
                for (int u = 0; u < 2; u++)
                    #pragma unroll
                    for (int mt = 0; mt < 2; mt++) {
                        mma_f16(acc[mt][4*jp + 2*u],     ah[mt], bh[u][0], bh[u][1]);
                        mma_f16(acc[mt][4*jp + 2*u + 1], ah[mt], bh[u][2], bh[u][3]);
                    }
            }
        }
    }
}

// ---- V projection: fp16 1-term, PERM fp16 output -> gv16 ----
__global__ void __launch_bounds__(256, 2) gemm_v()
{
    extern __shared__ char smem[];
    GemmCtx g; gemm_init(g, smem);
    const int m0 = (blockIdx.x >> 4) * 128, n0 = (blockIdx.x & 15) * 128;

    const int sr = g.tid >> 1, sc = (g.tid & 1) * 16;
    const __half* pa_h = gx16  + (size_t)(m0 + sr) * 2048 + sc;
    const __half* pb_h = gwv16 + (size_t)(n0 + sr) * 2048 + sc;

    float acc[2][8][4];
    #pragma unroll
    for (int mt = 0; mt < 2; mt++)
        #pragma unroll
        for (int nt = 0; nt < 8; nt++)
            #pragma unroll
            for (int i = 0; i < 4; i++) acc[mt][nt][i] = 0.f;

    gemm1_body(g, pa_h, pb_h, acc);

    #pragma unroll
    for (int mt = 0; mt < 2; mt++) {
        #pragma unroll
        for (int nt = 0; nt < 8; nt++) {
            int r  = m0 + g.wm * 32 + mt * 16 + (g.l >> 2);
            int cc = n0 + g.wn * 64 + nt * 8 + 2 * (g.l & 3);
            int b = r >> 11, s = r & 2047, h = cc >> 6, d = cc & 63;
            size_t base = (((size_t)(b * 32 + h)) * 2048 + s) * 64 + d;
            *reinterpret_cast<uint32_t*>(gv16 + base) =
                pack_h16(acc[mt][nt][0], acc[mt][nt][1]);
            *reinterpret_cast<uint32_t*>(gv16 + base + 8 * 64) =
                pack_h16(acc[mt][nt][2], acc[mt][nt][3]);
        }
    }
}

// ---- output projection: fp16 1-term, fp32 C ----
__global__ void __launch_bounds__(256, 2) gemm_out(float* __restrict__ Cf)
{
    extern __shared__ char smem[];
    GemmCtx g; gemm_init(g, smem);
    const int m0 = (blockIdx.x >> 4) * 128, n0 = (blockIdx.x & 15) * 128;

    const int sr = g.tid >> 1, sc = (g.tid & 1) * 16;
    const __half* pa_h = gc_h  + (size_t)(m0 + sr) * 2048 + sc;
    const __half* pb_h = gwo16 + (size_t)(n0 + sr) * 2048 + sc;

    float acc[2][8][4];
    #pragma unroll
    for (int mt = 0; mt < 2; mt++)
        #pragma unroll
        for (int nt = 0; nt < 8; nt++)
            #pragma unroll
            for (int i = 0; i < 4; i++) acc[mt][nt][i] = 0.f;

    gemm1_body(g, pa_h, pb_h, acc);

    #pragma unroll
    for (int mt = 0; mt < 2; mt++) {
        #pragma unroll
        for (int nt = 0; nt < 8; nt++) {
            int r  = m0 + g.wm * 32 + mt * 16 + (g.l >> 2);
            int cc = n0 + g.wn * 64 + nt * 8 + 2 * (g.l & 3);
            *reinterpret_cast<float2*>(Cf + (size_t)r * 2048 + cc) =
                make_float2(acc[mt][nt][0], acc[mt][nt][1]);
            *reinterpret_cast<float2*>(Cf + (size_t)(r + 8) * 2048 + cc) =
                make_float2(acc[mt][nt][2], acc[mt][nt][3]);
        }
    }
}

// ===========================================================================
// relative-position bucket (exact integer T5 formula) + bias table
// ===========================================================================
__device__ __forceinline__ int rel_bucket(int dist) {
    int rel = dist > 0 ? 16 : 0;
    int d = abs(dist);
    int sb;
    if (d < 8)       sb = d;
    else if (d < 12) sb = 8;
    else if (d < 16) sb = 9;
    else if (d < 23) sb = 10;
    else if (d < 32) sb = 11;
    else if (d < 46) sb = 12;
    else if (d < 64) sb = 13;
    else if (d < 91) sb = 14;
    else             sb = 15;
    return rel + sb;
}

__global__ void bias_table_kernel(const float* __restrict__ rel_bias) {
    int idx = blockIdx.x * blockDim.x + threadIdx.x;
    if (idx >= HH * 4095) return;
    int h = idx / 4095;
    int di = idx % 4095;
    g_biastab[h * 4096 + di] = rel_bias[rel_bucket(di - 2047) * HH + h];
}

// ===========================================================================
// FA2-style attention: QK bf16x3 (score path), PV 1-term fp16 (value path).
// KV tile 128 (16 iters) + folded bias write. ctx stored fp16-hi only.
// smem: Qh 16K | Ql 16K | 2 x { Kh 16K Kl 16K Vh 16K } | 2 x bias 1K = 130K
// ===========================================================================
#define AKV 49152
#define ABIAS (32768 + 2*AKV)
#define ASMEM_BYTES (ABIAS + 2*1024)

__global__ void __launch_bounds__(256, 1) attn_mma(float* __restrict__ out_bias)
{
    extern __shared__ char smem[];
    const uint32_t su = smem_to_u32(smem);
    const int tid = threadIdx.x, l = tid & 31, w = tid >> 5;
    const int grp = l >> 3, lr = l & 7;
    const int bh = blockIdx.y, h = bh & 31, b = bh >> 5;
    const int q0 = blockIdx.x * 128;
    const size_t bhoff = (size_t)bh * SS * HD;
    const int r2 = tid >> 1, hf = tid & 1;

    // Q tiles -> smem (part of group 0)
    {
        const __nv_bfloat16* sh = gq_h + bhoff + (size_t)(q0 + r2) * 64 + hf * 32;
        const __nv_bfloat16* sl = gq_l + bhoff + (size_t)(q0 + r2) * 64 + hf * 32;
        uint32_t dd = (uint32_t)(r2 * 128 + hf * 64);
        #pragma unroll
        for (int i = 0; i < 4; i++) {
            uint32_t o = dd + i * 16; o ^= (o >> 3) & 0x70;
            cp16(su + o,         sh + i * 8);
            cp16(su + 16384 + o, sl + i * 8);
        }
    }

    // KV + bias issue for ktile kt: Kh, Kl (bf16), Vh (fp16)
    auto issue_kv = [&](int kt) {
        uint32_t sb = su + 32768 + (uint32_t)(kt & 1) * AKV;
        size_t off = bhoff + (size_t)(kt * 128 + r2) * 64 + hf * 32;
        const uint32_t dd = (uint32_t)(r2 * 128 + hf * 64);
        #pragma unroll
        for (int i = 0; i < 4; i++) {
            uint32_t o = dd + i * 16; o ^= (o >> 3) & 0x70;
            cp16(sb + o,         gk_h + off + i * 8);
            cp16(sb + 16384 + o, gk_l + off + i * 8);
            cp16(sb + 32768 + o, gv16 + off + i * 8);
        }
        int w0 = kt * 128 - q0 + 1920;
        cp4(su + ABIAS + (uint32_t)(kt & 1) * 1024 + tid * 4,
            &g_biastab[h * 4096 + w0 + tid]);
    };
    issue_kv(0); CP_COMMIT();
    issue_kv(1); CP_COMMIT();

    float o[8][4];
    #pragma unroll
    for (int nt = 0; nt < 8; nt++)
        #pragma unroll
        for (int i = 0; i < 4; i++) o[nt][i] = 0.f;
    float mrow[2] = {-1e30f, -1e30f};
    float lrow[2] = {0.f, 0.f};

    const uint32_t qbase  = (uint32_t)((w * 16 + lr + (grp & 1) * 8) * 128 + (grp >> 1) * 16);
    const uint32_t kvbase = (uint32_t)((lr + (grp >> 1) * 8) * 128 + (grp & 1) * 16);

    for (int kt = 0; kt < 16; kt++) {
        CP_WAIT(1);
        __syncthreads();
        const uint32_t SB = su + 32768 + (uint32_t)(kt & 1) * AKV;
        const float* bsm = reinterpret_cast<const float*>(
            smem + ABIAS + (kt & 1) * 1024);

        // ---- S = Q K^T (bf16x3, term-major) ----
        float s[16][4];
        #pragma unroll
        for (int j = 0; j < 16; j++)
            #pragma unroll
            for (int i = 0; i < 4; i++) s[j][i] = 0.f;

        #pragma unroll
        for (int ks = 0; ks < 4; ks++) {
            uint32_t qo = qbase + (uint32_t)(ks * 32); qo ^= (qo >> 3) & 0x70;
            uint32_t ah[4], al[4];
            ldx4(ah, su + qo);
            ldx4(al, su + 16384 + qo);
            #pragma unroll
            for (int jp = 0; jp < 4; jp++) {
                uint32_t kh[2][4], kl[2][4];
                #pragma unroll
                for (int u = 0; u < 2; u++) {
                    uint32_t ko = kvbase + (uint32_t)((2*jp + u) * 2048 + ks * 32);
                    ko ^= (ko >> 3) & 0x70;
                    ldx4(kh[u], SB + ko);
                    ldx4(kl[u], SB + 16384 + ko);
                }
                #pragma unroll
                for (int u = 0; u < 2; u++) {
                    mma_bf16(s[4*jp + 2*u],     ah, kh[u][0], kh[u][1]);
                    mma_bf16(s[4*jp + 2*u + 1], ah, kh[u][2], kh[u][3]);
                }
                #pragma unroll
                for (int u = 0; u < 2; u++) {
                    mma_bf16(s[4*jp + 2*u],     ah, kl[u][0], kl[u][1]);
                    mma_bf16(s[4*jp + 2*u + 1], ah, kl[u][2], kl[u][3]);
                }
                #pragma unroll
                for (int u = 0; u < 2; u++) {
                    mma_bf16(s[4*jp + 2*u],     al, kh[u][0], kh[u][1]);
                    mma_bf16(s[4*jp + 2*u + 1], al, kh[u][2], kh[u][3]);
                }
            }
        }

        // ---- bias + online softmax ----
        const int bb = 127 - (w * 16 + (l >> 2)) + 2 * (l & 3);
        #pragma unroll
        for (int j = 0; j < 16; j++) {
            s[j][0] += bsm[bb + 8*j];
            s[j][1] += bsm[bb + 8*j + 1];
            s[j][2] += bsm[bb + 8*j - 8];
            s[j][3] += bsm[bb + 8*j - 7];
        }
        #pragma unroll
        for (int u = 0; u < 2; u++) {
            float mx = -1e30f;
            #pragma unroll
            for (int j = 0; j < 16; j++)
                mx = fmaxf(mx, fmaxf(s[j][2*u], s[j][2*u+1]));
            mx = fmaxf(mx, __shfl_xor_sync(0xffffffffu, mx, 1));
            mx = fmaxf(mx, __shfl_xor_sync(0xffffffffu, mx, 2));
            float mnew = fmaxf(mrow[u], mx);
            float scale = __expf(mrow[u] - mnew);
            mrow[u] = mnew;
            float sum = 0.f;
            #pragma unroll
            for (int j = 0; j < 16; j++) {
                float p0 = __expf(s[j][2*u]   - mnew);
                float p1 = __expf(s[j][2*u+1] - mnew);
                s[j][2*u] = p0; s[j][2*u+1] = p1;
                sum += p0 + p1;
            }
            sum += __shfl_xor_sync(0xffffffffu, sum, 1);
            sum += __shfl_xor_sync(0xffffffffu, sum, 2);
            lrow[u] = lrow[u] * scale + sum;
            #pragma unroll
            for (int nt = 0; nt < 8; nt++) {
                o[nt][2*u]   *= scale;
                o[nt][2*u+1] *= scale;
            }
        }

        // ---- O += P V (1-term fp16: P fp16-hi, V fp16-hi) ----
        #pragma unroll
        for (int ks = 0; ks < 8; ks++) {
            uint32_t aph[4];
            aph[0] = pack_h16(s[2*ks][0],   s[2*ks][1]);
            aph[1] = pack_h16(s[2*ks][2],   s[2*ks][3]);
            aph[2] = pack_h16(s[2*ks+1][0], s[2*ks+1][1]);
            aph[3] = pack_h16(s[2*ks+1][2], s[2*ks+1][3]);
            #pragma unroll
            for (int dp = 0; dp < 2; dp++) {
                uint32_t vh[2][4];
                #pragma unroll
                for (int u = 0; u < 2; u++) {
                    uint32_t vo = kvbase + (uint32_t)(ks * 2048 + (2*dp + u) * 32);
                    vo ^= (vo >> 3) & 0x70;
                    ldx4t(vh[u], SB + 32768 + vo);
                }
                #pragma unroll
                for (int u = 0; u < 2; u++) {
                    mma_f16(o[4*dp + 2*u],     aph, vh[u][0], vh[u][2]);
                    mma_f16(o[4*dp + 2*u + 1], aph, vh[u][1], vh[u][3]);
                }
            }
        }

        // ---- folded position_bias materialization (b==0 CTAs only) ----
        if (b == 0) {
            const int q = tid >> 1;          // 0..127
            const int kh2 = (tid & 1) * 64;  // 0 or 64
            float* dst = out_bias + ((size_t)h * 2048 + (q0 + q)) * 2048
                                  + kt * 128 + kh2;
            const int bidx = kh2 - q + 127;
            #pragma unroll
            for (int i = 0; i < 16; i++) {
                *reinterpret_cast<float4*>(dst + 4*i) =
                    make_float4(bsm[bidx + 4*i],     bsm[bidx + 4*i + 1],
                                bsm[bidx + 4*i + 2], bsm[bidx + 4*i + 3]);
            }
        }

        __syncthreads();
        if (kt + 2 < 16) issue_kv(kt + 2);
        CP_COMMIT();
    }

    // ---- epilogue: normalize, fp16-hi store of ctx ----
    const float inv0 = 1.f / lrow[0], inv1 = 1.f / lrow[1];
    const int rg0 = b * 2048 + q0 + w * 16 + (l >> 2);
    const size_t base0 = (size_t)rg0 * 2048 + h * 64 + 2 * (l & 3);
    const size_t base1 = base0 + (size_t)8 * 2048;
    #pragma unroll
    for (int nt = 0; nt < 8; nt++) {
        float a0 = o[nt][0] * inv0, a1 = o[nt][1] * inv0;
        float a2 = o[nt][2] * inv1, a3 = o[nt][3] * inv1;
        *reinterpret_cast<uint32_t*>(gc_h + base0 + nt * 8) = pack_h16(a0, a1);
        *reinterpret_cast<uint32_t*>(gc_h + base1 + nt * 8) = pack_h16(a2, a3);
    }
}

// ===========================================================================

extern "C" void kernel_launch(void* const* d_in, const int* in_sizes, int n_in,
                              void* d_out, int out_size)
{
    (void)in_sizes; (void)n_in; (void)out_size;
    const float* x  = (const float*)d_in[0];
    const float* wq = (const float*)d_in[1];
    const float* wk = (const float*)d_in[2];
    const float* wv = (const float*)d_in[3];
    const float* wo = (const float*)d_in[4];
    const float* rb = (const float*)d_in[5];
    float* out      = (float*)d_out;
    float* out_bias = out + (size_t)BB * SS * MD;

    __nv_bfloat16 *wqh,*wql,*wkh,*wkl;
    __half *wvh,*woh;
    cudaGetSymbolAddress((void**)&wqh, gwq_h); cudaGetSymbolAddress((void**)&wql, gwq_l);
    cudaGetSymbolAddress((void**)&wkh, gwk_h); cudaGetSymbolAddress((void**)&wkl, gwk_l);
    cudaGetSymbolAddress((void**)&wvh, gwv16); cudaGetSymbolAddress((void**)&woh, gwo16);

    cudaFuncSetAttribute(gemm_qk,  cudaFuncAttributeMaxDynamicSharedMemorySize, GSMEM_BYTES);
    cudaFuncSetAttribute(gemm_v,   cudaFuncAttributeMaxDynamicSharedMemorySize, O1SMEM_BYTES);
    cudaFuncSetAttribute(gemm_out, cudaFuncAttributeMaxDynamicSharedMemorySize, O1SMEM_BYTES);
    cudaFuncSetAttribute(attn_mma, cudaFuncAttributeMaxDynamicSharedMemorySize, ASMEM_BYTES);

    // one-shot conversions + bias table
    convert_x_kernel<<<(MTOT*MD/8 + 255)/256, 256>>>(x, MTOT*MD/8);
    convert_kernel<<<(MD*MD/8 + 255)/256, 256>>>(wq, wqh, wql, MD*MD/8);
    convert_kernel<<<(MD*MD/8 + 255)/256, 256>>>(wk, wkh, wkl, MD*MD/8);
    convert_f16h_kernel<<<(MD*MD/8 + 255)/256, 256>>>(wv, wvh, MD*MD/8);
    convert_f16h_kernel<<<(MD*MD/8 + 255)/256, 256>>>(wo, woh, MD*MD/8);
    bias_table_kernel<<<(HH*4095 + 255)/256, 256>>>(rb);

    // projections
    gemm_qk<<<1024, 256, GSMEM_BYTES>>>();
    gemm_v<<<512, 256, O1SMEM_BYTES>>>();

    // attention (QK bf16x3, PV fp16 1-term) + position_bias materialization
    attn_mma<<<dim3(16, 64), 256, ASMEM_BYTES>>>(out_bias);

    // output projection (fp16 1-term, fp32 out)
    gemm_out<<<512, 256, O1SMEM_BYTES>>>(out);
}

// round 16
// speedup vs baseline: 1.4558x; 1.0292x over previous
#include <cuda_runtime.h>
#include <cuda_bf16.h>
#include <cuda_fp16.h>
#include <cstdint>
#include <math.h>

#define BB 2
#define SS 2048
#define HH 32
#define HD 64
#define MD 2048
#define MTOT (BB*SS)

// ---------------- device scratch (static, no allocation) ----------------
__device__ __nv_bfloat16 gx_h[MTOT*MD],  gx_l[MTOT*MD];
__device__ __half        gx16[MTOT*MD];                    // x fp16 (V path)
__device__ __nv_bfloat16 gwq_h[MD*MD],   gwq_l[MD*MD];
__device__ __nv_bfloat16 gwk_h[MD*MD],   gwk_l[MD*MD];
__device__ __half        gwv16[MD*MD];                     // wv fp16-hi (1-term)
__device__ __half        gwo16[MD*MD];                     // wo fp16-hi (1-term)
__device__ __nv_bfloat16 gq_h[MTOT*MD],  gq_l[MTOT*MD];    // [bh][s][64]
__device__ __nv_bfloat16 gk_h[MTOT*MD],  gk_l[MTOT*MD];
__device__ __half        gv16[MTOT*MD];                    // v fp16-hi only
__device__ __half        gc_h[MTOT*MD];                    // ctx fp16-hi only
__device__ float g_biastab[HH*4096];

// ---------------- small helpers ----------------
__device__ __forceinline__ uint32_t smem_to_u32(const void* p) {
    uint32_t a;
    asm("{ .reg .u64 t; cvta.to.shared.u64 t, %1; cvt.u32.u64 %0, t; }" : "=r"(a) : "l"(p));
    return a;
}
__device__ __forceinline__ void cp16(uint32_t dst, const void* src) {
    asm volatile("cp.async.cg.shared.global [%0], [%1], 16;" :: "r"(dst), "l"(src));
}
__device__ __forceinline__ void cp4(uint32_t dst, const void* src) {
    asm volatile("cp.async.ca.shared.global [%0], [%1], 4;" :: "r"(dst), "l"(src));
}
#define CP_COMMIT() asm volatile("cp.async.commit_group;" ::: "memory")
#define CP_WAIT(n)  asm volatile("cp.async.wait_group %0;" :: "n"(n) : "memory")

__device__ __forceinline__ void ldx4(uint32_t* r, uint32_t addr) {
    asm volatile("ldmatrix.sync.aligned.m8n8.x4.shared.b16 {%0,%1,%2,%3}, [%4];"
                 : "=r"(r[0]), "=r"(r[1]), "=r"(r[2]), "=r"(r[3]) : "r"(addr));
}
__device__ __forceinline__ void ldx4t(uint32_t* r, uint32_t addr) {
    asm volatile("ldmatrix.sync.aligned.m8n8.x4.trans.shared.b16 {%0,%1,%2,%3}, [%4];"
                 : "=r"(r[0]), "=r"(r[1]), "=r"(r[2]), "=r"(r[3]) : "r"(addr));
}
__device__ __forceinline__ void mma_bf16(float* d, const uint32_t* a,
                                         uint32_t b0, uint32_t b1) {
    asm volatile(
        "mma.sync.aligned.m16n8k16.row.col.f32.bf16.bf16.f32 "
        "{%0,%1,%2,%3}, {%4,%5,%6,%7}, {%8,%9}, {%0,%1,%2,%3};"
        : "+f"(d[0]), "+f"(d[1]), "+f"(d[2]), "+f"(d[3])
        : "r"(a[0]), "r"(a[1]), "r"(a[2]), "r"(a[3]), "r"(b0), "r"(b1));
}
__device__ __forceinline__ void mma_f16(float* d, const uint32_t* a,
                                        uint32_t b0, uint32_t b1) {
    asm volatile(
        "mma.sync.aligned.m16n8k16.row.col.f32.f16.f16.f32 "
        "{%0,%1,%2,%3}, {%4,%5,%6,%7}, {%8,%9}, {%0,%1,%2,%3};"
        : "+f"(d[0]), "+f"(d[1]), "+f"(d[2]), "+f"(d[3])
        : "r"(a[0]), "r"(a[1]), "r"(a[2]), "r"(a[3]), "r"(b0), "r"(b1));
}

__device__ __forceinline__ uint32_t pack_hi(float a, float b) {
    return __byte_perm(__float_as_uint(a), __float_as_uint(b), 0x7632);
}
__device__ __forceinline__ uint32_t pack_lo_res(float a, float b) {
    float ra = a - __uint_as_float(__float_as_uint(a) & 0xffff0000u);
    float rb = b - __uint_as_float(__float_as_uint(b) & 0xffff0000u);
    uint32_t r;
    asm("cvt.rn.bf16x2.f32 %0, %1, %2;" : "=r"(r) : "f"(rb), "f"(ra));
    return r;
}
__device__ __forceinline__ uint32_t pack_h16(float a, float b) {
    uint32_t r;
    asm("cvt.rn.f16x2.f32 %0, %1, %2;" : "=r"(r) : "f"(b), "f"(a));
    return r;
}

// x -> bf16 hi/lo + fp16 single, one pass
__global__ void convert_x_kernel(const float* __restrict__ in, int n8) {
    int i = blockIdx.x * blockDim.x + threadIdx.x;
    if (i >= n8) return;
    float4 f0 = reinterpret_cast<const float4*>(in)[2*i];
    float4 f1 = reinterpret_cast<const float4*>(in)[2*i + 1];
    reinterpret_cast<uint4*>(gx_h)[i] = make_uint4(
        pack_hi(f0.x, f0.y), pack_hi(f0.z, f0.w),
        pack_hi(f1.x, f1.y), pack_hi(f1.z, f1.w));
    reinterpret_cast<uint4*>(gx_l)[i] = make_uint4(
        pack_lo_res(f0.x, f0.y), pack_lo_res(f0.z, f0.w),
        pack_lo_res(f1.x, f1.y), pack_lo_res(f1.z, f1.w));
    reinterpret_cast<uint4*>(gx16)[i] = make_uint4(
        pack_h16(f0.x, f0.y), pack_h16(f0.z, f0.w),
        pack_h16(f1.x, f1.y), pack_h16(f1.z, f1.w));
}

// all 4 weights in one kernel: sel 0=wq(bf16), 1=wk(bf16), 2=wv(f16h), 3=wo(f16h)
#define W_N8 (MD*MD/8)
__global__ void convert_w_kernel(const float* __restrict__ wq,
                                 const float* __restrict__ wk,
                                 const float* __restrict__ wv,
                                 const float* __restrict__ wo) {
    int i = blockIdx.x * blockDim.x + threadIdx.x;
    int sel = i >> 19;                 // W_N8 = 2^19
    int j = i & (W_N8 - 1);
    const float* src = (sel == 0) ? wq : (sel == 1) ? wk : (sel == 2) ? wv : wo;
    float4 f0 = reinterpret_cast<const float4*>(src)[2*j];
    float4 f1 = reinterpret_cast<const float4*>(src)[2*j + 1];
    if (sel < 2) {
        __nv_bfloat16* hi = sel ? gwk_h : gwq_h;
        __nv_bfloat16* lo = sel ? gwk_l : gwq_l;
        reinterpret_cast<uint4*>(hi)[j] = make_uint4(
            pack_hi(f0.x, f0.y), pack_hi(f0.z, f0.w),
            pack_hi(f1.x, f1.y), pack_hi(f1.z, f1.w));
        reinterpret_cast<uint4*>(lo)[j] = make_uint4(
            pack_lo_res(f0.x, f0.y), pack_lo_res(f0.z, f0.w),
            pack_lo_res(f1.x, f1.y), pack_lo_res(f1.z, f1.w));
    } else {
        __half* hi = (sel == 2) ? gwv16 : gwo16;
        reinterpret_cast<uint4*>(hi)[j] = make_uint4(
            pack_h16(f0.x, f0.y), pack_h16(f0.z, f0.w),
            pack_h16(f1.x, f1.y), pack_h16(f1.z, f1.w));
    }
}

// ===========================================================================
// Shared warp/thread mapping for 128x128 tile GEMMs
// ===========================================================================
struct GemmCtx {
    uint32_t su;
    int tid, l, w, wm, wn, grp, lr;
    uint32_t a_row[2], b_row[4], a_c16, b_c16;
};

__device__ __forceinline__ void gemm_init(GemmCtx& g, char* smem) {
    g.su = smem_to_u32(smem);
    g.tid = threadIdx.x;
    g.l = g.tid & 31; g.w = g.tid >> 5;
    g.wm = g.w >> 1;  g.wn = g.w & 1;          // 4m x 2n warp grid
    g.grp = g.l >> 3; g.lr = g.l & 7;
    #pragma unroll
    for (int mt = 0; mt < 2; mt++)
        g.a_row[mt] = (uint32_t)((g.wm * 32 + mt * 16 + g.lr + (g.grp & 1) * 8) * 64);
    #pragma unroll
    for (int j = 0; j < 4; j++)
        g.b_row[j] = (uint32_t)((g.wn * 64 + j * 16 + g.lr + (g.grp >> 1) * 8) * 64);
    g.a_c16 = (uint32_t)(g.grp >> 1) * 16;
    g.b_c16 = (uint32_t)(g.grp & 1) * 16;
}

// ===========================================================================
// bf16x3 GEMM body: K-chunk 32, 3-stage (96KB), 2 CTAs/SM.
// stage: Ah 8K | Al 8K | Bh 8K | Bl 8K = 32K
// ===========================================================================
#define GSTAGE 32768
#define GSMEM_BYTES (3 * GSTAGE)

__device__ __forceinline__ void issue_g(uint32_t sb,
    const __nv_bfloat16* a_h, const __nv_bfloat16* a_l,
    const __nv_bfloat16* b_h, const __nv_bfloat16* b_l, int tid)
{
    uint32_t o = (uint32_t)((tid >> 1) * 64 + (tid & 1) * 32);
    uint32_t o0 = o ^ ((o >> 3) & 0x30);
    uint32_t o1 = o0 ^ 16;
    cp16(sb + o0,         a_h);     cp16(sb + o1,         a_h + 8);
    cp16(sb + 8192  + o0, a_l);     cp16(sb + 8192  + o1, a_l + 8);
    cp16(sb + 16384 + o0, b_h);     cp16(sb + 16384 + o1, b_h + 8);
    cp16(sb + 24576 + o0, b_l);     cp16(sb + 24576 + o1, b_l + 8);
}

__device__ __forceinline__ void gemm_body(
    GemmCtx& g,
    const __nv_bfloat16* pa_h, const __nv_bfloat16* pa_l,
    const __nv_bfloat16* pb_h, const __nv_bfloat16* pb_l,
    float acc[2][8][4])
{
    issue_g(g.su,          pa_h,      pa_l,      pb_h,      pb_l,      g.tid); CP_COMMIT();
    issue_g(g.su + GSTAGE, pa_h + 32, pa_l + 32, pb_h + 32, pb_l + 32, g.tid); CP_COMMIT();

    for (int c = 0; c < 64; c++) {
        CP_WAIT(1);
        __syncthreads();
        if (c + 2 < 64) {
            int k0 = (c + 2) * 32;
            issue_g(g.su + (uint32_t)((c + 2) % 3) * GSTAGE,
                    pa_h + k0, pa_l + k0, pb_h + k0, pb_l + k0, g.tid);
        }
        CP_COMMIT();

        const uint32_t cur = g.su + (uint32_t)(c % 3) * GSTAGE;

        #pragma unroll
        for (int ks = 0; ks < 2; ks++) {
            uint32_t ah[2][4], al[2][4];
            #pragma unroll
            for (int mt = 0; mt < 2; mt++) {
                uint32_t off = g.a_row[mt] + (uint32_t)(ks * 32) + g.a_c16;
                off ^= (off >> 3) & 0x30;
                ldx4(ah[mt], cur + off);
                ldx4(al[mt], cur + 8192 + off);
            }
            #pragma unroll
            for (int jp = 0; jp < 2; jp++) {
                uint32_t bh[2][4], bl[2][4];
                #pragma unroll
                for (int u = 0; u < 2; u++) {
                    uint32_t off = g.b_row[2*jp + u] + (uint32_t)(ks * 32) + g.b_c16;
                    off ^= (off >> 3) & 0x30;
                    ldx4(bh[u], cur + 16384 + off);
                    ldx4(bl[u], cur + 24576 + off);
                }
                #pragma unroll
                for (int u = 0; u < 2; u++)
                    #pragma unroll
                    for (int mt = 0; mt < 2; mt++) {
                        mma_bf16(acc[mt][4*jp + 2*u],     ah[mt], bh[u][0], bh[u][1]);
                        mma_bf16(acc[mt][4*jp + 2*u + 1], ah[mt], bh[u][2], bh[u][3]);
                    }
                #pragma unroll
                for (int u = 0; u < 2; u++)
                    #pragma unroll
                    for (int mt = 0; mt < 2; mt++) {
                        mma_bf16(acc[mt][4*jp + 2*u],     ah[mt], bl[u][0], bl[u][1]);
                        mma_bf16(acc[mt][4*jp + 2*u + 1], ah[mt], bl[u][2], bl[u][3]);
                    }
                #pragma unroll
                for (int u = 0; u < 2; u++)
                    #pragma unroll
                    for (int mt = 0; mt < 2; mt++) {
                        mma_bf16(acc[mt][4*jp + 2*u],     al[mt], bh[u][0], bh[u][1]);
                        mma_bf16(acc[mt][4*jp + 2*u + 1], al[mt], bh[u][2], bh[u][3]);
                    }
            }
        }
    }
}

// ===========================================================================
// fp16 1-term GEMM body (A fp16, B fp16).
// stage: Ah 8K | Bh 8K = 16K (uses first 48K of the 96K dynamic smem).
// ===========================================================================
#define O1STAGE 16384
#define O1SMEM_BYTES (3 * O1STAGE)

__device__ __forceinline__ void issue_1(uint32_t sb,
    const __half* a_h, const __half* b_h, int tid)
{
    uint32_t o = (uint32_t)((tid >> 1) * 64 + (tid & 1) * 32);
    uint32_t o0 = o ^ ((o >> 3) & 0x30);
    uint32_t o1 = o0 ^ 16;
    cp16(sb + o0,        a_h);     cp16(sb + o1,        a_h + 8);
    cp16(sb + 8192 + o0, b_h);     cp16(sb + 8192 + o1, b_h + 8);
}

__device__ __forceinline__ void gemm1_body(
    GemmCtx& g, const __half* pa_h, const __half* pb_h, float acc[2][8][4])
{
    issue_1(g.su,           pa_h,      pb_h,      g.tid); CP_COMMIT();
    issue_1(g.su + O1STAGE, pa_h + 32, pb_h + 32, g.tid); CP_COMMIT();

    for (int c = 0; c < 64; c++) {
        CP_WAIT(1);
        __syncthreads();
        if (c + 2 < 64) {
            int k0 = (c + 2) * 32;
            issue_1(g.su + (uint32_t)((c + 2) % 3) * O1STAGE,
                    pa_h + k0, pb_h + k0, g.tid);
        }
        CP_COMMIT();

        const uint32_t cur = g.su + (uint32_t)(c % 3) * O1STAGE;

        #pragma unroll
        for (int ks = 0; ks < 2; ks++) {
            uint32_t ah[2][4];
            #pragma unroll
            for (int mt = 0; mt < 2; mt++) {
                uint32_t off = g.a_row[mt] + (uint32_t)(ks * 32) + g.a_c16;
                off ^= (off >> 3) & 0x30;
                ldx4(ah[mt], cur + off);
            }
            #pragma unroll
            for (int jp = 0; jp < 2; jp++) {
                uint32_t bh[2][4];
                #pragma unroll
                for (int u = 0; u < 2; u++) {
                    uint32_t off = g.b_row[2*jp + u] + (uint32_t)(ks * 32) + g.b_c16;
                    off ^= (off >> 3) & 0x30;
                    ldx4(bh[u], cur + 8192 + off);
                }
                #pragma unroll
                for (int u = 0; u < 2; u++)
                    #pragma unroll
                    for (int mt = 0; mt < 2; mt++) {
                        mma_f16(acc[mt][4*jp + 2*u],     ah[mt], bh[u][0], bh[u][1]);
                        mma_f16(acc[mt][4*jp + 2*u + 1], ah[mt], bh[u][2], bh[u][3]);
                    }
            }
        }
    }
}

// ---- fused QKV projections: grid 1536 = 3 x 512 tiles (wsel-major).
// wsel 0/1: bf16x3 -> q/k bf16 hi/lo. wsel 2: fp16 1-term -> v fp16.
__global__ void __launch_bounds__(256, 2) gemm_qkv()
{
    extern __shared__ char smem[];
    GemmCtx g; gemm_init(g, smem);

    const int wsel = blockIdx.x >> 9;
    const int tile = blockIdx.x & 511;
    const int m0 = (tile >> 4) * 128, n0 = (tile & 15) * 128;
    const int sr = g.tid >> 1, sc = (g.tid & 1) * 16;

    float acc[2][8][4];
    #pragma unroll
    for (int mt = 0; mt < 2; mt++)
        #pragma unroll
        for (int nt = 0; nt < 8; nt++)
            #pragma unroll
            for (int i = 0; i < 4; i++) acc[mt][nt][i] = 0.f;

    if (wsel == 2) {
        const __half* pa_h = gx16  + (size_t)(m0 + sr) * 2048 + sc;
        const __half* pb_h = gwv16 + (size_t)(n0 + sr) * 2048 + sc;
        gemm1_body(g, pa_h, pb_h, acc);
        #pragma unroll
        for (int mt = 0; mt < 2; mt++) {
            #pragma unroll
            for (int nt = 0; nt < 8; nt++) {
                int r  = m0 + g.wm * 32 + mt * 16 + (g.l >> 2);
                int cc = n0 + g.wn * 64 + nt * 8 + 2 * (g.l & 3);
                int b = r >> 11, s = r & 2047, h = cc >> 6, d = cc & 63;
                size_t base = (((size_t)(b * 32 + h)) * 2048 + s) * 64 + d;
                *reinterpret_cast<uint32_t*>(gv16 + base) =
                    pack_h16(acc[mt][nt][0], acc[mt][nt][1]);
                *reinterpret_cast<uint32_t*>(gv16 + base + 8 * 64) =
                    pack_h16(acc[mt][nt][2], acc[mt][nt][3]);
            }
        }
    } else {
        const __nv_bfloat16* Bh = wsel ? gwk_h : gwq_h;
        const __nv_bfloat16* Bl = wsel ? gwk_l : gwq_l;
        __nv_bfloat16* Ch = wsel ? gk_h : gq_h;
        __nv_bfloat16* Cl = wsel ? gk_l : gq_l;
        const __nv_bfloat16* pa_h = gx_h + (size_t)(m0 + sr) * 2048 + sc;
        const __nv_bfloat16* pa_l = gx_l + (size_t)(m0 + sr) * 2048 + sc;
        const __nv_bfloat16* pb_h = Bh   + (size_t)(n0 + sr) * 2048 + sc;
        const __nv_bfloat16* pb_l = Bl   + (size_t)(n0 + sr) * 2048 + sc;
        gemm_body(g, pa_h, pa_l, pb_h, pb_l, acc);
        #pragma unroll
        for (int mt = 0; mt < 2; mt++) {
            #pragma unroll
            for (int nt = 0; nt < 8; nt++) {
                int r  = m0 + g.wm * 32 + mt * 16 + (g.l >> 2);
                int cc = n0 + g.wn * 64 + nt * 8 + 2 * (g.l & 3);
                int b = r >> 11, s = r & 2047, h = cc >> 6, d = cc & 63;
                size_t base = (((size_t)(b * 32 + h)) * 2048 + s) * 64 + d;
                *reinterpret_cast<uint32_t*>(Ch + base) =
                    pack_hi(acc[mt][nt][0], acc[mt][nt][1]);
                *reinterpret_cast<uint32_t*>(Cl + base) =
                    pack_lo_res(acc[mt][nt][0], acc[mt][nt][1]);
                *reinterpret_cast<uint32_t*>(Ch + base + 8 * 64) =
                    pack_hi(acc[mt][nt][2], acc[mt][nt][3]);
                *reinterpret_cast<uint32_t*>(Cl + base + 8 * 64) =
                    pack_lo_res(acc[mt][nt][2], acc[mt][nt][3]);
            }
        }
    }
}

// ---- output projection: fp16 1-term, fp32 C ----
__global__ void __launch_bounds__(256, 2) gemm_out(float* __restrict__ Cf)
{
    extern __shared__ char smem[];
    GemmCtx g; gemm_init(g, smem);
    const int m0 = (blockIdx.x >> 4) * 128, n0 = (blockIdx.x & 15) * 128;

    const int sr = g.tid >> 1, sc = (g.tid & 1) * 16;
    const __half* pa_h = gc_h  + (size_t)(m0 + sr) * 2048 + sc;
    const __half* pb_h = gwo16 + (size_t)(n0 + sr) * 2048 + sc;

    float acc[2][8][4];
    #pragma unroll
    for (int mt = 0; mt < 2; mt++)
        #pragma unroll
        for (int nt = 0; nt < 8; nt++)
            #pragma unroll
            for (int i = 0; i < 4; i++) acc[mt][nt][i] = 0.f;

    gemm1_body(g, pa_h, pb_h, acc);

    #pragma unroll
    for (int mt = 0; mt < 2; mt++) {
        #pragma unroll
        for (int nt = 0; nt < 8; nt++) {
            int r  = m0 + g.wm * 32 + mt * 16 + (g.l >> 2);
            int cc = n0 + g.wn * 64 + nt * 8 + 2 * (g.l & 3);
            *reinterpret_cast<float2*>(Cf + (size_t)r * 2048 + cc) =
                make_float2(acc[mt][nt][0], acc[mt][nt][1]);
            *reinterpret_cast<float2*>(Cf + (size_t)(r + 8) * 2048 + cc) =
                make_float2(acc[mt][nt][2], acc[mt][nt][3]);
        }
    }
}

// ===========================================================================
// relative-position bucket (exact integer T5 formula) + bias table
// ===========================================================================
__device__ __forceinline__ int rel_bucket(int dist) {
    int rel = dist > 0 ? 16 : 0;
    int d = abs(dist);
    int sb;
    if (d < 8)       sb = d;
    else if (d < 12) sb = 8;
    else if (d < 16) sb = 9;
    else if (d < 23) sb = 10;
    else if (d < 32) sb = 11;
    else if (d < 46) sb = 12;
    else if (d < 64) sb = 13;
    else if (d < 91) sb = 14;
    else             sb = 15;
    return rel + sb;
}

__global__ void bias_table_kernel(const float* __restrict__ rel_bias) {
    int idx = blockIdx.x * blockDim.x + threadIdx.x;
    if (idx >= HH * 4095) return;
    int h = idx / 4095;
    int di = idx % 4095;
    g_biastab[h * 4096 + di] = rel_bias[rel_bucket(di - 2047) * HH + h];
}

// ===========================================================================
// FA2-style attention: QK bf16x3 (score path), PV 1-term fp16 (value path).
// Q fragments hoisted to registers before the KV loop (Q invariant over kt).
// KV tile 128 (16 iters) + folded bias write. ctx stored fp16-hi only.
// smem: Qh 16K | Ql 16K | 2 x { Kh 16K Kl 16K Vh 16K } | 2 x bias 1K = 130K
// ===========================================================================
#define AKV 49152
#define ABIAS (32768 + 2*AKV)
#define ASMEM_BYTES (ABIAS + 2*1024)

__global__ void __launch_bounds__(256, 1) attn_mma(float* __restrict__ out_bias)
{
    extern __shared__ char smem[];
    const uint32_t su = smem_to_u32(smem);
    const int tid = threadIdx.x, l = tid & 31, w = tid >> 5;
    const int grp = l >> 3, lr = l & 7;
    const int bh = blockIdx.y, h = bh & 31, b = bh >> 5;
    const int q0 = blockIdx.x * 128;
    const size_t bhoff = (size_t)bh * SS * HD;
    const int r2 = tid >> 1, hf = tid & 1;

    // Q tiles -> smem (part of group 0)
    {
        const __nv_bfloat16* sh = gq_h + bhoff + (size_t)(q0 + r2) * 64 + hf * 32;
        const __nv_bfloat16* sl = gq_l + bhoff + (size_t)(q0 + r2) * 64 + hf * 32;
        uint32_t dd = (uint32_t)(r2 * 128 + hf * 64);
        #pragma unroll
        for (int i = 0; i < 4; i++) {
            uint32_t o = dd + i * 16; o ^= (o >> 3) & 0x70;
            cp16(su + o,         sh + i * 8);
            cp16(su + 16384 + o, sl + i * 8);
        }
    }

    // KV + bias issue for ktile kt: Kh, Kl (bf16), Vh (fp16)
    auto issue_kv = [&](int kt) {
        uint32_t sb = su + 32768 + (uint32_t)(kt & 1) * AKV;
        size_t off = bhoff + (size_t)(kt * 128 + r2) * 64 + hf * 32;
        const uint32_t dd = (uint32_t)(r2 * 128 + hf * 64);
        #pragma unroll
        for (int i = 0; i < 4; i++) {
            uint32_t o = dd + i * 16; o ^= (o >> 3) & 0x70;
            cp16(sb + o,         gk_h + off + i * 8);
            cp16(sb + 16384 + o, gk_l + off + i * 8);
            cp16(sb + 32768 + o, gv16 + off + i * 8);
        }
        int w0 = kt * 128 - q0 + 1920;
        cp4(su + ABIAS + (uint32_t)(kt & 1) * 1024 + tid * 4,
            &g_biastab[h * 4096 + w0 + tid]);
    };
    issue_kv(0); CP_COMMIT();
    issue_kv(1); CP_COMMIT();

    float o[8][4];
    #pragma unroll
    for (int nt = 0; nt < 8; nt++)
        #pragma unroll
        for (int i = 0; i < 4; i++) o[nt][i] = 0.f;
    float mrow[2] = {-1e30f, -1e30f};
    float lrow[2] = {0.f, 0.f};

    const uint32_t qbase  = (uint32_t)((w * 16 + lr + (grp & 1) * 8) * 128 + (grp >> 1) * 16);
    const uint32_t kvbase = (uint32_t)((lr + (grp >> 1) * 8) * 128 + (grp & 1) * 16);

    // wait for group 0 (Q + kv0), then hoist ALL Q fragments into registers
    CP_WAIT(1);
    __syncthreads();
    uint32_t qa_h[4][4], qa_l[4][4];
    #pragma unroll
    for (int ks = 0; ks < 4; ks++) {
        uint32_t qo = qbase + (uint32_t)(ks * 32); qo ^= (qo >> 3) & 0x70;
        ldx4(qa_h[ks], su + qo);
        ldx4(qa_l[ks], su + 16384 + qo);
    }

    for (int kt = 0; kt < 16; kt++) {
        if (kt > 0) { CP_WAIT(1); __syncthreads(); }
        const uint32_t SB = su + 32768 + (uint32_t)(kt & 1) * AKV;
        const float* bsm = reinterpret_cast<const float*>(
            smem + ABIAS + (kt & 1) * 1024);

        // ---- S = Q K^T (bf16x3, term-major, Q frags from registers) ----
        float s[16][4];
        #pragma unroll
        for (int j = 0; j < 16; j++)
            #pragma unroll
            for (int i = 0; i < 4; i++) s[j][i] = 0.f;

        #pragma unroll
        for (int ks = 0; ks < 4; ks++) {
            #pragma unroll
            for (int jp = 0; jp < 4; jp++) {
                uint32_t kh[2][4], kl[2][4];
                #pragma unroll
                for (int u = 0; u < 2; u++) {
                    uint32_t ko = kvbase + (uint32_t)((2*jp + u) * 2048 + ks * 32);
                    ko ^= (ko >> 3) & 0x70;
                    ldx4(kh[u], SB + ko);
                    ldx4(kl[u], SB + 16384 + ko);
                }
                #pragma unroll
                for (int u = 0; u < 2; u++) {
                    mma_bf16(s[4*jp + 2*u],     qa_h[ks], kh[u][0], kh[u][1]);
                    mma_bf16(s[4*jp + 2*u + 1], qa_h[ks], kh[u][2], kh[u][3]);
                }
                #pragma unroll
                for (int u = 0; u < 2; u++) {
                    mma_bf16(s[4*jp + 2*u],     qa_h[ks], kl[u][0], kl[u][1]);
                    mma_bf16(s[4*jp + 2*u + 1], qa_h[ks], kl[u][2], kl[u][3]);
                }
                #pragma unroll
                for (int u = 0; u < 2; u++) {
                    mma_bf16(s[4*jp + 2*u],     qa_l[ks], kh[u][0], kh[u][1]);
                    mma_bf16(s[4*jp + 2*u + 1], qa_l[ks], kh[u][2], kh[u][3]);
                }
            }
        }

        // ---- bias + online softmax ----
        const int bb = 127 - (w * 16 + (l >> 2)) + 2 * (l & 3);
        #pragma unroll
        for (int j = 0; j < 16; j++) {
            s[j][0] += bsm[bb + 8*j];
            s[j][1] += bsm[bb + 8*j + 1];
            s[j][2] += bsm[bb + 8*j - 8];
            s[j][3] += bsm[bb + 8*j - 7];
        }
        #pragma unroll
        for (int u = 0; u < 2; u++) {
            float mx = -1e30f;
            #pragma unroll
            for (int j = 0; j < 16; j++)
                mx = fmaxf(mx, fmaxf(s[j][2*u], s[j][2*u+1]));
            mx = fmaxf(mx, __shfl_xor_sync(0xffffffffu, mx, 1));
            mx = fmaxf(mx, __shfl_xor_sync(0xffffffffu, mx, 2));
            float mnew = fmaxf(mrow[u], mx);
            float scale = __expf(mrow[u] - mnew);
            mrow[u] = mnew;
            float sum = 0.f;
            #pragma unroll
            for (int j = 0; j < 16; j++) {
                float p0 = __expf(s[j][2*u]   - mnew);
                float p1 = __expf(s[j][2*u+1] - mnew);
                s[j][2*u] = p0; s[j][2*u+1] = p1;
                sum += p0 + p1;
            }
            sum += __shfl_xor_sync(0xffffffffu, sum, 1);
            sum += __shfl_xor_sync(0xffffffffu, sum, 2);
            lrow[u] = lrow[u] * scale + sum;
            #pragma unroll
            for (int nt = 0; nt < 8; nt++) {
                o[nt][2*u]   *= scale;
                o[nt][2*u+1] *= scale;
            }
        }

        // ---- O += P V (1-term fp16: P fp16-hi, V fp16-hi) ----
        #pragma unroll
        for (int ks = 0; ks < 8; ks++) {
            uint32_t aph[4];
            aph[0] = pack_h16(s[2*ks][0],   s[2*ks][1]);
            aph[1] = pack_h16(s[2*ks][2],   s[2*ks][3]);
            aph[2] = pack_h16(s[2*ks+1][0], s[2*ks+1][1]);
            aph[3] = pack_h16(s[2*ks+1][2], s[2*ks+1][3]);
            #pragma unroll
            for (int dp = 0; dp < 2; dp++) {
                uint32_t vh[2][4];
                #pragma unroll
                for (int u = 0; u < 2; u++) {
                    uint32_t vo = kvbase + (uint32_t)(ks * 2048 + (2*dp + u) * 32);
                    vo ^= (vo >> 3) & 0x70;
                    ldx4t(vh[u], SB + 32768 + vo);
                }
                #pragma unroll
                for (int u = 0; u < 2; u++) {
                    mma_f16(o[4*dp + 2*u],     aph, vh[u][0], vh[u][2]);
                    mma_f16(o[4*dp + 2*u + 1], aph, vh[u][1], vh[u][3]);
                }
            }
        }

        // ---- folded position_bias materialization (b==0 CTAs only) ----
        if (b == 0) {
            const int q = tid >> 1;          // 0..127
            const int kh2 = (tid & 1) * 64;  // 0 or 64
            float* dst = out_bias + ((size_t)h * 2048 + (q0 + q)) * 2048
                                  + kt * 128 + kh2;
            const int bidx = kh2 - q + 127;
            #pragma unroll
            for (int i = 0; i < 16; i++) {
                *reinterpret_cast<float4*>(dst + 4*i) =
                    make_float4(bsm[bidx + 4*i],     bsm[bidx + 4*i + 1],
                                bsm[bidx + 4*i + 2], bsm[bidx + 4*i + 3]);
            }
        }

        __syncthreads();
        if (kt + 2 < 16) issue_kv(kt + 2);
        CP_COMMIT();
    }

    // ---- epilogue: normalize, fp16-hi store of ctx ----
    const float inv0 = 1.f / lrow[0], inv1 = 1.f / lrow[1];
    const int rg0 = b * 2048 + q0 + w * 16 + (l >> 2);
    const size_t base0 = (size_t)rg0 * 2048 + h * 64 + 2 * (l & 3);
    const size_t base1 = base0 + (size_t)8 * 2048;
    #pragma unroll
    for (int nt = 0; nt < 8; nt++) {
        float a0 = o[nt][0] * inv0, a1 = o[nt][1] * inv0;
        float a2 = o[nt][2] * inv1, a3 = o[nt][3] * inv1;
        *reinterpret_cast<uint32_t*>(gc_h + base0 + nt * 8) = pack_h16(a0, a1);
        *reinterpret_cast<uint32_t*>(gc_h + base1 + nt * 8) = pack_h16(a2, a3);
    }
}

// ===========================================================================

extern "C" void kernel_launch(void* const* d_in, const int* in_sizes, int n_in,
                              void* d_out, int out_size)
{
    (void)in_sizes; (void)n_in; (void)out_size;
    const float* x  = (const float*)d_in[0];
    const float* wq = (const float*)d_in[1];
    const float* wk = (const float*)d_in[2];
    const float* wv = (const float*)d_in[3];
    const float* wo = (const float*)d_in[4];
    const float* rb = (const float*)d_in[5];
    float* out      = (float*)d_out;
    float* out_bias = out + (size_t)BB * SS * MD;

    cudaFuncSetAttribute(gemm_qkv, cudaFuncAttributeMaxDynamicSharedMemorySize, GSMEM_BYTES);
    cudaFuncSetAttribute(gemm_out, cudaFuncAttributeMaxDynamicSharedMemorySize, O1SMEM_BYTES);
    cudaFuncSetAttribute(attn_mma, cudaFuncAttributeMaxDynamicSharedMemorySize, ASMEM_BYTES);

    // one-shot conversions + bias table
    convert_x_kernel<<<(MTOT*MD/8 + 255)/256, 256>>>(x, MTOT*MD/8);
    convert_w_kernel<<<(4*W_N8)/256, 256>>>(wq, wk, wv, wo);
    bias_table_kernel<<<(HH*4095 + 255)/256, 256>>>(rb);

    // fused Q/K/V projections in ONE launch (QK bf16x3, V fp16 1-term)
    gemm_qkv<<<1536, 256, GSMEM_BYTES>>>();

    // attention (QK bf16x3, PV fp16 1-term) + position_bias materialization
    attn_mma<<<dim3(16, 64), 256, ASMEM_BYTES>>>(out_bias);

    // output projection (fp16 1-term, fp32 out)
    gemm_out<<<512, 256, O1SMEM_BYTES>>>(out);
}